// round 9
// baseline (speedup 1.0000x reference)
#include <cuda_runtime.h>
#include <cuda_bf16.h>
#include <cstdint>
#include <cstddef>

typedef __nv_bfloat16 bf16;

#define NN 8192
#define STAGE_BYTES 49152u
#define SMEM_BYTES (2 * 49152)

// ---------------- device scratch (no allocs allowed; zero-init at load) ----
__device__ __align__(1024) bf16 g_ht_hi[256 * NN];           // transposed features [F][NN]
__device__ __align__(1024) bf16 g_ht_lo[256 * NN];
__device__ __align__(1024) bf16 g_catA_hi[(size_t)NN * 512]; // layer1 concat [h|support]
__device__ __align__(1024) bf16 g_catA_lo[(size_t)NN * 512];
__device__ __align__(1024) bf16 g_catB_hi[(size_t)NN * 256]; // layers 2-4 concat
__device__ __align__(1024) bf16 g_catB_lo[(size_t)NN * 256];
__device__ __align__(1024) bf16 g_wt_hi[163840];             // W^T all 4 layers
__device__ __align__(1024) bf16 g_wt_lo[163840];
__device__ __align__(1024) float g_part[16777216];           // split-K partials (64MB)

// ---------------- helpers ----------------
__device__ __forceinline__ uint32_t s2u(const void* p) {
    uint32_t a;
    asm("{ .reg .u64 t; cvta.to.shared.u64 t, %1; cvt.u32.u64 %0, t; }" : "=r"(a) : "l"(p));
    return a;
}

#define CP16(dst_u32, src_ptr) \
    asm volatile("cp.async.cg.shared.global [%0], [%1], 16;" :: "r"(dst_u32), "l"(src_ptr) : "memory")

__device__ __forceinline__ void ldsm4(uint32_t a[4], uint32_t addr) {
    asm volatile("ldmatrix.sync.aligned.m8n8.x4.shared.b16 {%0,%1,%2,%3}, [%4];"
                 : "=r"(a[0]), "=r"(a[1]), "=r"(a[2]), "=r"(a[3]) : "r"(addr));
}

__device__ __forceinline__ void mma16816(float c[4], const uint32_t a[4], const uint32_t b[2]) {
    asm volatile(
        "mma.sync.aligned.m16n8k16.row.col.f32.bf16.bf16.f32 "
        "{%0,%1,%2,%3}, {%4,%5,%6,%7}, {%8,%9}, {%0,%1,%2,%3};"
        : "+f"(c[0]), "+f"(c[1]), "+f"(c[2]), "+f"(c[3])
        : "r"(a[0]), "r"(a[1]), "r"(a[2]), "r"(a[3]), "r"(b[0]), "r"(b[1]));
}

__device__ __forceinline__ void split2(float v, bf16& h, bf16& l) {
    h = __float2bfloat16(v);
    l = __float2bfloat16(v - __bfloat162float(h));
}

// cvt two fp32 -> packed bf16x2 (first arg -> upper half, second -> lower half)
__device__ __forceinline__ uint32_t cvt2(float hi_el, float lo_el) {
    uint32_t r;
    asm("cvt.rn.bf16x2.f32 %0, %1, %2;" : "=r"(r) : "f"(hi_el), "f"(lo_el));
    return r;
}

// ---------------- prep kernels ----------------
// x [8192,256] fp32 -> catA cols [0,256) row-major split, ld=512
__global__ void k_xcat(const float4* __restrict__ x4, bf16* __restrict__ hi,
                       bf16* __restrict__ lo) {
    int idx = blockIdx.x * blockDim.x + threadIdx.x;  // 8192*64
    int row = idx >> 6, c4 = idx & 63;
    float4 v = x4[idx];
    size_t base = (size_t)row * 512 + c4 * 4;
    bf16 h0, h1, h2, h3, l0, l1, l2, l3;
    split2(v.x, h0, l0); split2(v.y, h1, l1);
    split2(v.z, h2, l2); split2(v.w, h3, l3);
    __nv_bfloat162* H = (__nv_bfloat162*)(hi + base);
    __nv_bfloat162* L = (__nv_bfloat162*)(lo + base);
    H[0] = __halves2bfloat162(h0, h1); H[1] = __halves2bfloat162(h2, h3);
    L[0] = __halves2bfloat162(l0, l1); L[1] = __halves2bfloat162(l2, l3);
}

// transpose + split: src [R, C] fp32 -> dst[c][r] split bf16 (dst ld = R)
__global__ void k_tsplit(const float* __restrict__ src, int R, int C,
                         bf16* __restrict__ dhi, bf16* __restrict__ dlo) {
    __shared__ float t[32][33];
    int bx = blockIdx.x * 32;
    int by = blockIdx.y * 32;
    int tx = threadIdx.x, ty = threadIdx.y;
    #pragma unroll
    for (int i = 0; i < 4; i++)
        t[ty + 8 * i][tx] = src[(size_t)(by + ty + 8 * i) * C + bx + tx];
    __syncthreads();
    #pragma unroll
    for (int i = 0; i < 4; i++) {
        int c = bx + ty + 8 * i;
        float v = t[tx][ty + 8 * i];
        bf16 h, l; split2(v, h, l);
        dhi[(size_t)c * R + by + tx] = h;
        dlo[(size_t)c * R + by + tx] = l;
    }
}

// split-K partial reduce: sum nparts fp32 partials, split-bf16 into cat buffer
__global__ void k_reduce(const float4* __restrict__ p, size_t pstride4, int nparts,
                         bf16* __restrict__ hi, bf16* __restrict__ lo, int F4, int ld) {
    int idx = blockIdx.x * blockDim.x + threadIdx.x;
    int row = idx / F4;
    int c4 = (idx - row * F4) * 4;
    float4 s = p[idx];
    for (int z = 1; z < nparts; ++z) {
        float4 t = p[idx + (size_t)z * pstride4];
        s.x += t.x; s.y += t.y; s.z += t.z; s.w += t.w;
    }
    bf16 h0, l0, h1, l1, h2, l2, h3, l3;
    split2(s.x, h0, l0); split2(s.y, h1, l1);
    split2(s.z, h2, l2); split2(s.w, h3, l3);
    __nv_bfloat162* H = (__nv_bfloat162*)(hi + (size_t)row * ld + c4);
    __nv_bfloat162* L = (__nv_bfloat162*)(lo + (size_t)row * ld + c4);
    H[0] = __halves2bfloat162(h0, h1); H[1] = __halves2bfloat162(h2, h3);
    L[0] = __halves2bfloat162(l0, l1); L[1] = __halves2bfloat162(l2, l3);
}

// ---------------- split-bf16 3-product HMMA GEMM ----------------
// 128 threads, 4 warps (2m x 2n), per-warp m32 x n64. BM=64, BN=128.
// 2 stages x 48KB -> 2 CTAs/SM. Split-K via blockIdx.z, uneven chunk ranges.
// AFP32=0: A is bf16 hi/lo pair. Stage: Ah[64][128B]@0, Al@8192, Bh@16384, Bl@32768
// AFP32=1: A is fp32 (adj), converted to hi/lo frags in-register.
//          Stage: Afp32[64][256B]@0 (16B-granule XOR swizzle), Bh@16384, Bl@32768
struct Frags {
    uint32_t ah[2][4], al[2][4], bh[4][4], bl[4][4];
};
struct ACtx {
    uint32_t rb[2][2];   // stage-relative row base per (mi, h)
    uint32_t xr, cp16, w8;
};

template <int AFP32>
__device__ __forceinline__ void load_stage(
    uint32_t sb, int stage, int kc,
    const void* A1, const void* A2, int lda,
    const bf16* Bh, const bf16* Bl, int ldb,
    int m0, int n0, int tid) {
    uint32_t st = sb + (uint32_t)stage * STAGE_BYTES;
    if (AFP32) {
        const float* Af = (const float*)A1;
        #pragma unroll
        for (int i = 0; i < 8; ++i) {       // A: 1024 x 16B fp32
            int g = tid + (i << 7);
            int row = g >> 4;
            int cb = (g & 15) << 4;
            uint32_t dst = st + (uint32_t)(row * 256)
                         + (uint32_t)(cb ^ ((row & 7) << 4));
            CP16(dst, (const char*)(Af + (size_t)(m0 + row) * lda + kc) + cb);
        }
    } else {
        #pragma unroll
        for (int i = 0; i < 8; ++i) {       // A: 1024 x 16B (hi+lo bf16)
            int g = tid + (i << 7);
            int sub = g >> 9;
            int idx = g & 511;
            int row = idx >> 3;
            int cb = (idx & 7) << 4;
            uint32_t dst = st + (uint32_t)(sub * 8192) + (uint32_t)(row * 128)
                         + (uint32_t)(cb ^ ((row & 7) << 4));
            const bf16* srcb = sub ? (const bf16*)A2 : (const bf16*)A1;
            CP16(dst, (const char*)(srcb + (size_t)(m0 + row) * lda + kc) + cb);
        }
    }
    #pragma unroll
    for (int i = 0; i < 16; ++i) {          // B: 2048 x 16B (hi+lo)
        int g = tid + (i << 7);
        int sub = g >> 10;
        int idx = g & 1023;
        int row = idx >> 3;
        int cb = (idx & 7) << 4;
        uint32_t dst = st + 16384u + (uint32_t)(sub * 16384) + (uint32_t)(row * 128)
                     + (uint32_t)(cb ^ ((row & 7) << 4));
        const bf16* srcb = sub ? Bl : Bh;
        CP16(dst, (const char*)(srcb + (size_t)(n0 + row) * ldb + kc) + cb);
    }
}

// build ah/al frags for (mi, kq) from fp32 smem tile (truncation split)
__device__ __forceinline__ void afrag_f32(uint32_t st, const ACtx& cx, int mi, int kq,
                                          uint32_t ah[4], uint32_t al[4]) {
    #pragma unroll
    for (int kk = 0; kk < 2; ++kk) {
        #pragma unroll
        for (int h = 0; h < 2; ++h) {
            uint32_t addr = st + cx.rb[mi][h]
                          + ((((uint32_t)(64 * kq + 32 * kk)) + cx.cp16) ^ cx.xr) + cx.w8;
            uint32_t v0, v1;
            asm volatile("ld.shared.v2.b32 {%0,%1}, [%2];"
                         : "=r"(v0), "=r"(v1) : "r"(addr));
            uint32_t hi = __byte_perm(v0, v1, 0x7632);
            float l0 = __uint_as_float(v0) - __uint_as_float(v0 & 0xffff0000u);
            float l1 = __uint_as_float(v1) - __uint_as_float(v1 & 0xffff0000u);
            int idx = h + kk * 2;
            ah[idx] = hi;
            al[idx] = cvt2(l1, l0);
        }
    }
}

template <int AFP32>
__device__ __forceinline__ void frag_load(uint32_t st, uint32_t aB, uint32_t bB, int kq,
                                          uint32_t acol, uint32_t axr,
                                          uint32_t bcol, uint32_t bxr,
                                          const ACtx& cx, Frags& f) {
    if (AFP32) {
        afrag_f32(st, cx, 0, kq, f.ah[0], f.al[0]);
        afrag_f32(st, cx, 1, kq, f.ah[1], f.al[1]);
    } else {
        uint32_t ac = ((uint32_t)(kq * 32) + acol) ^ axr;
        #pragma unroll
        for (int mi = 0; mi < 2; ++mi) {
            ldsm4(f.ah[mi], aB + (uint32_t)(mi * 2048) + ac);
            ldsm4(f.al[mi], aB + 8192u + (uint32_t)(mi * 2048) + ac);
        }
    }
    uint32_t bc = ((uint32_t)(kq * 32) + bcol) ^ bxr;
    #pragma unroll
    for (int j = 0; j < 4; ++j) {
        ldsm4(f.bh[j], bB + (uint32_t)(j * 2048) + bc);
        ldsm4(f.bl[j], bB + 16384u + (uint32_t)(j * 2048) + bc);
    }
}

__device__ __forceinline__ void frag_mma(float acc[2][8][4], const Frags& f) {
    #pragma unroll
    for (int mi = 0; mi < 2; ++mi)
        #pragma unroll
        for (int ni = 0; ni < 8; ++ni)
            mma16816(acc[mi][ni], f.ah[mi], &f.bh[ni >> 1][(ni & 1) * 2]);
    #pragma unroll
    for (int mi = 0; mi < 2; ++mi)
        #pragma unroll
        for (int ni = 0; ni < 8; ++ni)
            mma16816(acc[mi][ni], f.ah[mi], &f.bl[ni >> 1][(ni & 1) * 2]);
    #pragma unroll
    for (int mi = 0; mi < 2; ++mi)
        #pragma unroll
        for (int ni = 0; ni < 8; ++ni)
            mma16816(acc[mi][ni], f.al[mi], &f.bh[ni >> 1][(ni & 1) * 2]);
}

template <int AFP32>
__global__ void __launch_bounds__(128, 2)
k_gemm(const void* __restrict__ A1, const void* __restrict__ A2, int lda,
       const bf16* __restrict__ Bh, const bf16* __restrict__ Bl, int ldb,
       int K, int mode, int Ncols, const float* __restrict__ bias,
       bf16* __restrict__ orm_hi, bf16* __restrict__ orm_lo, int ld_rm,
       bf16* __restrict__ ot_hi, bf16* __restrict__ ot_lo,
       float* __restrict__ of) {
    extern __shared__ char smem[];
    const int tid = threadIdx.x;
    const uint32_t sb = s2u(smem);
    const int m0 = (int)blockIdx.y * 64;
    const int n0 = (int)blockIdx.x * 128;
    const int CT = K >> 6;
    const int nz = (int)gridDim.z;
    const int c0 = (int)((size_t)blockIdx.z * CT / nz);
    const int c1 = (int)(((size_t)blockIdx.z + 1) * CT / nz);
    const int lane = tid & 31, wid = tid >> 5;
    const int wm = wid >> 1, wn = wid & 1;
    const int lg = lane >> 3, lr = lane & 7;

    // bf16 A ldsm roles
    const int arow = wm * 32 + (lg & 1) * 8 + lr;
    const uint32_t acol = (uint32_t)((lg >> 1) * 16);
    const uint32_t axr = (uint32_t)((arow & 7) << 4);
    // B ldsm roles
    const int brow = wn * 64 + (lg >> 1) * 8 + lr;
    const uint32_t bcol = (uint32_t)((lg & 1) * 16);
    const uint32_t bxr = (uint32_t)((brow & 7) << 4);
    // fp32 A frag roles
    ACtx cx;
    {
        int fr = lane >> 2, fc = lane & 3;
        #pragma unroll
        for (int mi = 0; mi < 2; ++mi)
            #pragma unroll
            for (int h = 0; h < 2; ++h)
                cx.rb[mi][h] = (uint32_t)((wm * 32 + mi * 16 + fr + 8 * h) * 256);
        cx.xr = (uint32_t)(fr << 4);
        cx.cp16 = (uint32_t)((fc >> 1) << 4);
        cx.w8 = (uint32_t)((fc & 1) << 3);
    }

    float acc[2][8][4] = {};

    load_stage<AFP32>(sb, 0, c0 << 6, A1, A2, lda, Bh, Bl, ldb, m0, n0, tid);
    asm volatile("cp.async.commit_group;" ::: "memory");
    load_stage<AFP32>(sb, 1, (c0 + 1) << 6, A1, A2, lda, Bh, Bl, ldb, m0, n0, tid);
    asm volatile("cp.async.commit_group;" ::: "memory");

    for (int c = c0; c < c1; ++c) {
        asm volatile("cp.async.wait_group 1;" ::: "memory");
        __syncthreads();

        uint32_t st = sb + (uint32_t)(((c - c0) & 1) * STAGE_BYTES);
        uint32_t aB = st + (uint32_t)(arow * 128);
        uint32_t bB = st + 16384u + (uint32_t)(brow * 128);

        Frags f;
        #pragma unroll
        for (int kq = 0; kq < 3; ++kq) {
            frag_load<AFP32>(st, aB, bB, kq, acol, axr, bcol, bxr, cx, f);
            frag_mma(acc, f);
        }
        frag_load<AFP32>(st, aB, bB, 3, acol, axr, bcol, bxr, cx, f);
        __syncthreads();
        int nc = c + 2;
        if (nc < c1)
            load_stage<AFP32>(sb, (c - c0) & 1, nc << 6, A1, A2, lda, Bh, Bl, ldb, m0, n0, tid);
        asm volatile("cp.async.commit_group;" ::: "memory");
        frag_mma(acc, f);
    }

    // ---------------- epilogue ----------------
    if (mode == 3) of += (size_t)blockIdx.z * NN * Ncols;
    #pragma unroll
    for (int mi = 0; mi < 2; ++mi) {
        int r0 = m0 + wm * 32 + mi * 16 + (lane >> 2);
        #pragma unroll
        for (int ni = 0; ni < 8; ++ni) {
            int c = n0 + wn * 64 + ni * 8 + ((lane & 3) << 1);
            float v0 = acc[mi][ni][0], v1 = acc[mi][ni][1];
            float v2 = acc[mi][ni][2], v3 = acc[mi][ni][3];
            if (mode == 3) {
                *(float2*)(of + (size_t)r0 * Ncols + c)       = make_float2(v0, v1);
                *(float2*)(of + (size_t)(r0 + 8) * Ncols + c) = make_float2(v2, v3);
            } else if (mode == 2) {
                if (c < Ncols) {
                    float b0v = bias[c], b1v = bias[c + 1];
                    *(float2*)(of + (size_t)r0 * Ncols + c)       = make_float2(v0 + b0v, v1 + b1v);
                    *(float2*)(of + (size_t)(r0 + 8) * Ncols + c) = make_float2(v2 + b0v, v3 + b1v);
                }
            } else {
                float b0v = bias[c], b1v = bias[c + 1];
                v0 = fmaxf(v0 + b0v, 0.f); v1 = fmaxf(v1 + b1v, 0.f);
                v2 = fmaxf(v2 + b0v, 0.f); v3 = fmaxf(v3 + b1v, 0.f);
                bf16 h0, l0, h1, l1, h2, l2, h3, l3;
                split2(v0, h0, l0); split2(v1, h1, l1);
                split2(v2, h2, l2); split2(v3, h3, l3);
                *(__nv_bfloat162*)(orm_hi + (size_t)r0 * ld_rm + c) = __halves2bfloat162(h0, h1);
                *(__nv_bfloat162*)(orm_lo + (size_t)r0 * ld_rm + c) = __halves2bfloat162(l0, l1);
                *(__nv_bfloat162*)(orm_hi + (size_t)(r0 + 8) * ld_rm + c) = __halves2bfloat162(h2, h3);
                *(__nv_bfloat162*)(orm_lo + (size_t)(r0 + 8) * ld_rm + c) = __halves2bfloat162(l2, l3);
                ot_hi[(size_t)c * NN + r0] = h0;       ot_lo[(size_t)c * NN + r0] = l0;
                ot_hi[(size_t)(c + 1) * NN + r0] = h1; ot_lo[(size_t)(c + 1) * NN + r0] = l1;
                ot_hi[(size_t)c * NN + r0 + 8] = h2;   ot_lo[(size_t)c * NN + r0 + 8] = l2;
                ot_hi[(size_t)(c + 1) * NN + r0 + 8] = h3;
                ot_lo[(size_t)(c + 1) * NN + r0 + 8] = l3;
            }
        }
    }
}

// ---------------- host ----------------
static void* symaddr(const void* sym) {
    void* p = nullptr;
    cudaGetSymbolAddress(&p, sym);
    return p;
}

extern "C" void kernel_launch(void* const* d_in, const int* in_sizes, int n_in,
                              void* d_out, int out_size) {
    (void)in_sizes; (void)n_in; (void)out_size;
    const float* x   = (const float*)d_in[0];
    const float* adj = (const float*)d_in[1];
    const float* W1  = (const float*)d_in[2];
    const float* b1  = (const float*)d_in[3];
    const float* W2  = (const float*)d_in[4];
    const float* b2  = (const float*)d_in[5];
    const float* W3  = (const float*)d_in[6];
    const float* b3  = (const float*)d_in[7];
    const float* W4  = (const float*)d_in[8];
    const float* b4  = (const float*)d_in[9];

    bf16* ht_hi   = (bf16*)symaddr(g_ht_hi);
    bf16* ht_lo   = (bf16*)symaddr(g_ht_lo);
    bf16* catA_hi = (bf16*)symaddr(g_catA_hi);
    bf16* catA_lo = (bf16*)symaddr(g_catA_lo);
    bf16* catB_hi = (bf16*)symaddr(g_catB_hi);
    bf16* catB_lo = (bf16*)symaddr(g_catB_lo);
    bf16* wt_hi   = (bf16*)symaddr(g_wt_hi);
    bf16* wt_lo   = (bf16*)symaddr(g_wt_lo);
    float* part   = (float*)symaddr(g_part);

    cudaFuncSetAttribute(k_gemm<0>, cudaFuncAttributeMaxDynamicSharedMemorySize, SMEM_BYTES);
    cudaFuncSetAttribute(k_gemm<1>, cudaFuncAttributeMaxDynamicSharedMemorySize, SMEM_BYTES);

    // ---- prep ----
    k_xcat<<<2048, 256>>>((const float4*)x, catA_hi, catA_lo);
    k_tsplit<<<dim3(8, 256), dim3(32, 8)>>>(x, NN, 256, ht_hi, ht_lo);

    // ---- layer 1 aggregation: A = adj fp32 in-GEMM split (profiling target) ----
    k_gemm<1><<<dim3(2, 128, 2), 128, SMEM_BYTES>>>(adj, nullptr, NN, ht_hi, ht_lo, NN,
        NN, 3, 256, nullptr, nullptr, nullptr, 0, nullptr, nullptr, part);
    k_reduce<<<2048, 256>>>((const float4*)part, (size_t)NN * 256 / 4, 2,
                            catA_hi + 256, catA_lo + 256, 64, 512);

    k_tsplit<<<dim3(4, 16), dim3(32, 8)>>>(W1, 512, 128, wt_hi,          wt_lo);
    k_tsplit<<<dim3(4, 8),  dim3(32, 8)>>>(W2, 256, 128, wt_hi + 65536,  wt_lo + 65536);
    k_tsplit<<<dim3(4, 8),  dim3(32, 8)>>>(W3, 256, 128, wt_hi + 98304,  wt_lo + 98304);
    k_tsplit<<<dim3(2, 8),  dim3(32, 8)>>>(W4, 256, 64,  wt_hi + 131072, wt_lo + 131072);

    // ---- layer 1 linear ----
    k_gemm<0><<<dim3(1, 128, 1), 128, SMEM_BYTES>>>(catA_hi, catA_lo, 512, wt_hi, wt_lo, 512,
        512, 1, 128, b1, catB_hi, catB_lo, 256, ht_hi, ht_lo, nullptr);

    // ---- layer 2 ----
    k_gemm<1><<<dim3(1, 128, 9), 128, SMEM_BYTES>>>(adj, nullptr, NN, ht_hi, ht_lo, NN,
        NN, 3, 128, nullptr, nullptr, nullptr, 0, nullptr, nullptr, part);
    k_reduce<<<1024, 256>>>((const float4*)part, (size_t)NN * 128 / 4, 9,
                            catB_hi + 128, catB_lo + 128, 32, 256);
    k_gemm<0><<<dim3(1, 128, 1), 128, SMEM_BYTES>>>(catB_hi, catB_lo, 256,
        wt_hi + 65536, wt_lo + 65536, 256,
        256, 1, 128, b2, catB_hi, catB_lo, 256, ht_hi, ht_lo, nullptr);

    // ---- layer 3 ----
    k_gemm<1><<<dim3(1, 128, 9), 128, SMEM_BYTES>>>(adj, nullptr, NN, ht_hi, ht_lo, NN,
        NN, 3, 128, nullptr, nullptr, nullptr, 0, nullptr, nullptr, part);
    k_reduce<<<1024, 256>>>((const float4*)part, (size_t)NN * 128 / 4, 9,
                            catB_hi + 128, catB_lo + 128, 32, 256);
    k_gemm<0><<<dim3(1, 128, 1), 128, SMEM_BYTES>>>(catB_hi, catB_lo, 256,
        wt_hi + 98304, wt_lo + 98304, 256,
        256, 1, 128, b3, catB_hi, catB_lo, 256, ht_hi, ht_lo, nullptr);

    // ---- layer 4 ----
    k_gemm<1><<<dim3(1, 128, 9), 128, SMEM_BYTES>>>(adj, nullptr, NN, ht_hi, ht_lo, NN,
        NN, 3, 128, nullptr, nullptr, nullptr, 0, nullptr, nullptr, part);
    k_reduce<<<1024, 256>>>((const float4*)part, (size_t)NN * 128 / 4, 9,
                            catB_hi + 128, catB_lo + 128, 32, 256);
    k_gemm<0><<<dim3(1, 128, 1), 128, SMEM_BYTES>>>(catB_hi, catB_lo, 256,
        wt_hi + 131072, wt_lo + 131072, 256,
        256, 2, 64, b4, nullptr, nullptr, 0, nullptr, nullptr, (float*)d_out);
}

// round 10
// speedup vs baseline: 1.1795x; 1.1795x over previous
#include <cuda_runtime.h>
#include <cuda_bf16.h>
#include <cstdint>
#include <cstddef>

typedef __nv_bfloat16 bf16;

#define NN 8192
#define STAGE_BYTES 49152u
#define SMEM_BYTES (2 * 49152)

// ---------------- device scratch (no allocs; zero-init at load) ----------------
__device__ __align__(1024) bf16 g_adj_hi[(size_t)NN * NN];
__device__ __align__(1024) bf16 g_adj_lo[(size_t)NN * NN];
__device__ __align__(1024) bf16 g_x_hi[NN * 256];            // x split, ld 256
__device__ __align__(1024) bf16 g_x_lo[NN * 256];
__device__ __align__(1024) bf16 g_hA_hi[NN * 128];           // layer outputs ping-pong
__device__ __align__(1024) bf16 g_hA_lo[NN * 128];
__device__ __align__(1024) bf16 g_hB_hi[NN * 128];
__device__ __align__(1024) bf16 g_hB_lo[NN * 128];
__device__ __align__(1024) bf16 g_yt_hi[128 * NN];           // y^T [128][NN]
__device__ __align__(1024) bf16 g_yt_lo[128 * NN];
__device__ __align__(1024) bf16 g_wt_hi[163840];             // W^T; L4 zero-padded to 128 rows
__device__ __align__(1024) bf16 g_wt_lo[163840];
__device__ __align__(1024) float g_z[NN * 128];              // reduced aggregation (fp32)
__device__ __align__(1024) float g_part[9 * NN * 128];       // split-K partials

// ---------------- helpers ----------------
__device__ __forceinline__ uint32_t s2u(const void* p) {
    uint32_t a;
    asm("{ .reg .u64 t; cvta.to.shared.u64 t, %1; cvt.u32.u64 %0, t; }" : "=r"(a) : "l"(p));
    return a;
}

#define CP16(dst_u32, src_ptr) \
    asm volatile("cp.async.cg.shared.global [%0], [%1], 16;" :: "r"(dst_u32), "l"(src_ptr) : "memory")

__device__ __forceinline__ void ldsm4(uint32_t a[4], uint32_t addr) {
    asm volatile("ldmatrix.sync.aligned.m8n8.x4.shared.b16 {%0,%1,%2,%3}, [%4];"
                 : "=r"(a[0]), "=r"(a[1]), "=r"(a[2]), "=r"(a[3]) : "r"(addr));
}

__device__ __forceinline__ void mma16816(float c[4], const uint32_t a[4], const uint32_t b[2]) {
    asm volatile(
        "mma.sync.aligned.m16n8k16.row.col.f32.bf16.bf16.f32 "
        "{%0,%1,%2,%3}, {%4,%5,%6,%7}, {%8,%9}, {%0,%1,%2,%3};"
        : "+f"(c[0]), "+f"(c[1]), "+f"(c[2]), "+f"(c[3])
        : "r"(a[0]), "r"(a[1]), "r"(a[2]), "r"(a[3]), "r"(b[0]), "r"(b[1]));
}

__device__ __forceinline__ void split2(float v, bf16& h, bf16& l) {
    h = __float2bfloat16(v);
    l = __float2bfloat16(v - __bfloat162float(h));
}

__device__ __forceinline__ uint32_t cvt2(float hi_el, float lo_el) {
    uint32_t r;
    asm("cvt.rn.bf16x2.f32 %0, %1, %2;" : "=r"(r) : "f"(hi_el), "f"(lo_el));
    return r;
}

// ---------------- prep kernels ----------------
// truncation split of adj: hi = top16 bits, lo = exact remainder; streaming
__global__ void k_split(const uint4* __restrict__ src, uint4* __restrict__ hi,
                        uint4* __restrict__ lo, size_t n8) {
    size_t i = (size_t)blockIdx.x * blockDim.x + threadIdx.x;
    size_t stride = (size_t)gridDim.x * blockDim.x;
    for (; i < n8; i += stride) {
        uint4 a = __ldcs(src + 2 * i);
        uint4 b = __ldcs(src + 2 * i + 1);
        uint32_t u[8] = {a.x, a.y, a.z, a.w, b.x, b.y, b.z, b.w};
        uint4 H, L;
        H.x = __byte_perm(u[0], u[1], 0x7632);
        H.y = __byte_perm(u[2], u[3], 0x7632);
        H.z = __byte_perm(u[4], u[5], 0x7632);
        H.w = __byte_perm(u[6], u[7], 0x7632);
        float l[8];
        #pragma unroll
        for (int j = 0; j < 8; ++j) {
            float f  = __uint_as_float(u[j]);
            float hf = __uint_as_float(u[j] & 0xffff0000u);
            l[j] = f - hf;
        }
        L.x = cvt2(l[1], l[0]);
        L.y = cvt2(l[3], l[2]);
        L.z = cvt2(l[5], l[4]);
        L.w = cvt2(l[7], l[6]);
        __stcs(hi + i, H);
        __stcs(lo + i, L);
    }
}

// x [8192,256] fp32 -> split row-major ld 256
__global__ void k_xcat(const float4* __restrict__ x4, bf16* __restrict__ hi,
                       bf16* __restrict__ lo) {
    int idx = blockIdx.x * blockDim.x + threadIdx.x;  // 8192*64
    float4 v = x4[idx];
    size_t base = (size_t)idx * 4;
    bf16 h0, h1, h2, h3, l0, l1, l2, l3;
    split2(v.x, h0, l0); split2(v.y, h1, l1);
    split2(v.z, h2, l2); split2(v.w, h3, l3);
    __nv_bfloat162* H = (__nv_bfloat162*)(hi + base);
    __nv_bfloat162* L = (__nv_bfloat162*)(lo + base);
    H[0] = __halves2bfloat162(h0, h1); H[1] = __halves2bfloat162(h2, h3);
    L[0] = __halves2bfloat162(l0, l1); L[1] = __halves2bfloat162(l2, l3);
}

// transpose + split: src [R, C] fp32 -> dst[c][r] split bf16 (dst ld = R)
__global__ void k_tsplit(const float* __restrict__ src, int R, int C,
                         bf16* __restrict__ dhi, bf16* __restrict__ dlo) {
    __shared__ float t[32][33];
    int bx = blockIdx.x * 32;
    int by = blockIdx.y * 32;
    int tx = threadIdx.x, ty = threadIdx.y;
    #pragma unroll
    for (int i = 0; i < 4; i++)
        t[ty + 8 * i][tx] = src[(size_t)(by + ty + 8 * i) * C + bx + tx];
    __syncthreads();
    #pragma unroll
    for (int i = 0; i < 4; i++) {
        int c = bx + ty + 8 * i;
        float v = t[tx][ty + 8 * i];
        bf16 h, l; split2(v, h, l);
        dhi[(size_t)c * R + by + tx] = h;
        dlo[(size_t)c * R + by + tx] = l;
    }
}

// sum nparts fp32 partials -> fp32 z buffer
__global__ void k_reducef(const float4* __restrict__ p, int nparts,
                          float4* __restrict__ z) {
    int idx = blockIdx.x * blockDim.x + threadIdx.x;   // NN*128/4
    float4 s = p[idx];
    #pragma unroll 8
    for (int q = 1; q < nparts; ++q) {
        float4 t = p[idx + (size_t)q * (NN * 128 / 4)];
        s.x += t.x; s.y += t.y; s.z += t.z; s.w += t.w;
    }
    z[idx] = s;
}

// ---------------- split-bf16 3-product HMMA GEMM ----------------
// 128 threads, 4 warps (2m x 2n), BM=64, BN=128. 2 stages x 48KB, 2 CTAs/SM.
// Split-K via blockIdx.z (uneven chunk ranges).
// mode 3: raw fp32 partials -> of + z*NN*Ncols
// mode 4: relu(v + z + bias) -> split row-major orm (ld_rm)
// mode 5: v + z + bias -> fp32 of (ld Ncols), guard c < Ncols
// mode 6: split -> transposed ot only (ld NN)
__device__ __forceinline__ void load_stage(
    uint32_t sb, int stage, int kc,
    const bf16* Ah, const bf16* Al, int lda,
    const bf16* Bh, const bf16* Bl, int ldb,
    int m0, int n0, int tid) {
    uint32_t st = sb + (uint32_t)stage * STAGE_BYTES;
    #pragma unroll
    for (int i = 0; i < 8; ++i) {           // A: 1024 x 16B (hi+lo)
        int g = tid + (i << 7);
        int sub = g >> 9;
        int idx = g & 511;
        int row = idx >> 3;
        int cb = (idx & 7) << 4;
        uint32_t dst = st + (uint32_t)(sub * 8192) + (uint32_t)(row * 128)
                     + (uint32_t)(cb ^ ((row & 7) << 4));
        const bf16* srcb = sub ? Al : Ah;
        CP16(dst, (const char*)(srcb + (size_t)(m0 + row) * lda + kc) + cb);
    }
    #pragma unroll
    for (int i = 0; i < 16; ++i) {          // B: 2048 x 16B (hi+lo)
        int g = tid + (i << 7);
        int sub = g >> 10;
        int idx = g & 1023;
        int row = idx >> 3;
        int cb = (idx & 7) << 4;
        uint32_t dst = st + 16384u + (uint32_t)(sub * 16384) + (uint32_t)(row * 128)
                     + (uint32_t)(cb ^ ((row & 7) << 4));
        const bf16* srcb = sub ? Bl : Bh;
        CP16(dst, (const char*)(srcb + (size_t)(n0 + row) * ldb + kc) + cb);
    }
}

struct Frags {
    uint32_t ah[2][4], al[2][4], bh[4][4], bl[4][4];
};

__device__ __forceinline__ void frag_load(uint32_t aB, uint32_t bB, int kq,
                                          uint32_t acol, uint32_t axr,
                                          uint32_t bcol, uint32_t bxr, Frags& f) {
    uint32_t ac = ((uint32_t)(kq * 32) + acol) ^ axr;
    uint32_t bc = ((uint32_t)(kq * 32) + bcol) ^ bxr;
    #pragma unroll
    for (int mi = 0; mi < 2; ++mi) {
        ldsm4(f.ah[mi], aB + (uint32_t)(mi * 2048) + ac);
        ldsm4(f.al[mi], aB + 8192u + (uint32_t)(mi * 2048) + ac);
    }
    #pragma unroll
    for (int j = 0; j < 4; ++j) {
        ldsm4(f.bh[j], bB + (uint32_t)(j * 2048) + bc);
        ldsm4(f.bl[j], bB + 16384u + (uint32_t)(j * 2048) + bc);
    }
}

__device__ __forceinline__ void frag_mma(float acc[2][8][4], const Frags& f) {
    #pragma unroll
    for (int mi = 0; mi < 2; ++mi)
        #pragma unroll
        for (int ni = 0; ni < 8; ++ni)
            mma16816(acc[mi][ni], f.ah[mi], &f.bh[ni >> 1][(ni & 1) * 2]);
    #pragma unroll
    for (int mi = 0; mi < 2; ++mi)
        #pragma unroll
        for (int ni = 0; ni < 8; ++ni)
            mma16816(acc[mi][ni], f.ah[mi], &f.bl[ni >> 1][(ni & 1) * 2]);
    #pragma unroll
    for (int mi = 0; mi < 2; ++mi)
        #pragma unroll
        for (int ni = 0; ni < 8; ++ni)
            mma16816(acc[mi][ni], f.al[mi], &f.bh[ni >> 1][(ni & 1) * 2]);
}

__global__ void __launch_bounds__(128, 2)
k_gemm(const bf16* __restrict__ Ah, const bf16* __restrict__ Al, int lda,
       const bf16* __restrict__ Bh, const bf16* __restrict__ Bl, int ldb,
       int K, int mode, int Ncols, const float* __restrict__ bias,
       const float* __restrict__ zin,
       bf16* __restrict__ orm_hi, bf16* __restrict__ orm_lo, int ld_rm,
       bf16* __restrict__ ot_hi, bf16* __restrict__ ot_lo,
       float* __restrict__ of) {
    extern __shared__ char smem[];
    const int tid = threadIdx.x;
    const uint32_t sb = s2u(smem);
    const int m0 = (int)blockIdx.y * 64;
    const int n0 = (int)blockIdx.x * 128;
    const int CT = K >> 6;
    const int nz = (int)gridDim.z;
    const int c0 = (int)((size_t)blockIdx.z * CT / nz);
    const int c1 = (int)(((size_t)blockIdx.z + 1) * CT / nz);
    const int lane = tid & 31, wid = tid >> 5;
    const int wm = wid >> 1, wn = wid & 1;
    const int lg = lane >> 3, lr = lane & 7;

    const int arow = wm * 32 + (lg & 1) * 8 + lr;
    const uint32_t acol = (uint32_t)((lg >> 1) * 16);
    const uint32_t axr = (uint32_t)((arow & 7) << 4);
    const int brow = wn * 64 + (lg >> 1) * 8 + lr;
    const uint32_t bcol = (uint32_t)((lg & 1) * 16);
    const uint32_t bxr = (uint32_t)((brow & 7) << 4);

    float acc[2][8][4] = {};

    load_stage(sb, 0, c0 << 6, Ah, Al, lda, Bh, Bl, ldb, m0, n0, tid);
    asm volatile("cp.async.commit_group;" ::: "memory");
    load_stage(sb, 1, (c0 + 1) << 6, Ah, Al, lda, Bh, Bl, ldb, m0, n0, tid);
    asm volatile("cp.async.commit_group;" ::: "memory");

    for (int c = c0; c < c1; ++c) {
        asm volatile("cp.async.wait_group 1;" ::: "memory");
        __syncthreads();

        uint32_t st = sb + (uint32_t)(((c - c0) & 1) * STAGE_BYTES);
        uint32_t aB = st + (uint32_t)(arow * 128);
        uint32_t bB = st + 16384u + (uint32_t)(brow * 128);

        Frags f;
        #pragma unroll
        for (int kq = 0; kq < 3; ++kq) {
            frag_load(aB, bB, kq, acol, axr, bcol, bxr, f);
            frag_mma(acc, f);
        }
        frag_load(aB, bB, 3, acol, axr, bcol, bxr, f);
        __syncthreads();
        int nc = c + 2;
        if (nc < c1)
            load_stage(sb, (c - c0) & 1, nc << 6, Ah, Al, lda, Bh, Bl, ldb, m0, n0, tid);
        asm volatile("cp.async.commit_group;" ::: "memory");
        frag_mma(acc, f);
    }

    // ---------------- epilogue ----------------
    if (mode == 3) of += (size_t)blockIdx.z * NN * Ncols;
    #pragma unroll
    for (int mi = 0; mi < 2; ++mi) {
        int r0 = m0 + wm * 32 + mi * 16 + (lane >> 2);
        #pragma unroll
        for (int ni = 0; ni < 8; ++ni) {
            int c = n0 + wn * 64 + ni * 8 + ((lane & 3) << 1);
            float v0 = acc[mi][ni][0], v1 = acc[mi][ni][1];
            float v2 = acc[mi][ni][2], v3 = acc[mi][ni][3];
            if (mode == 3) {
                *(float2*)(of + (size_t)r0 * Ncols + c)       = make_float2(v0, v1);
                *(float2*)(of + (size_t)(r0 + 8) * Ncols + c) = make_float2(v2, v3);
            } else if (mode == 6) {
                bf16 h0, l0, h1, l1, h2, l2, h3, l3;
                split2(v0, h0, l0); split2(v1, h1, l1);
                split2(v2, h2, l2); split2(v3, h3, l3);
                ot_hi[(size_t)c * NN + r0] = h0;       ot_lo[(size_t)c * NN + r0] = l0;
                ot_hi[(size_t)(c + 1) * NN + r0] = h1; ot_lo[(size_t)(c + 1) * NN + r0] = l1;
                ot_hi[(size_t)c * NN + r0 + 8] = h2;   ot_lo[(size_t)c * NN + r0 + 8] = l2;
                ot_hi[(size_t)(c + 1) * NN + r0 + 8] = h3;
                ot_lo[(size_t)(c + 1) * NN + r0 + 8] = l3;
            } else {
                float b0v = bias[c], b1v = bias[c + 1];
                float2 za = *(const float2*)(zin + (size_t)r0 * 128 + c);
                float2 zb = *(const float2*)(zin + (size_t)(r0 + 8) * 128 + c);
                v0 += za.x + b0v; v1 += za.y + b1v;
                v2 += zb.x + b0v; v3 += zb.y + b1v;
                if (mode == 5) {
                    if (c < Ncols) {
                        *(float2*)(of + (size_t)r0 * Ncols + c)       = make_float2(v0, v1);
                        *(float2*)(of + (size_t)(r0 + 8) * Ncols + c) = make_float2(v2, v3);
                    }
                } else {  // mode 4
                    v0 = fmaxf(v0, 0.f); v1 = fmaxf(v1, 0.f);
                    v2 = fmaxf(v2, 0.f); v3 = fmaxf(v3, 0.f);
                    bf16 h0, l0, h1, l1, h2, l2, h3, l3;
                    split2(v0, h0, l0); split2(v1, h1, l1);
                    split2(v2, h2, l2); split2(v3, h3, l3);
                    *(__nv_bfloat162*)(orm_hi + (size_t)r0 * ld_rm + c) = __halves2bfloat162(h0, h1);
                    *(__nv_bfloat162*)(orm_lo + (size_t)r0 * ld_rm + c) = __halves2bfloat162(l0, l1);
                    *(__nv_bfloat162*)(orm_hi + (size_t)(r0 + 8) * ld_rm + c) = __halves2bfloat162(h2, h3);
                    *(__nv_bfloat162*)(orm_lo + (size_t)(r0 + 8) * ld_rm + c) = __halves2bfloat162(l2, l3);
                }
            }
        }
    }
}

// ---------------- host ----------------
static void* symaddr(const void* sym) {
    void* p = nullptr;
    cudaGetSymbolAddress(&p, sym);
    return p;
}

extern "C" void kernel_launch(void* const* d_in, const int* in_sizes, int n_in,
                              void* d_out, int out_size) {
    (void)in_sizes; (void)n_in; (void)out_size;
    const float* x   = (const float*)d_in[0];
    const float* adj = (const float*)d_in[1];
    const float* W1  = (const float*)d_in[2];
    const float* b1  = (const float*)d_in[3];
    const float* W2  = (const float*)d_in[4];
    const float* b2  = (const float*)d_in[5];
    const float* W3  = (const float*)d_in[6];
    const float* b3  = (const float*)d_in[7];
    const float* W4  = (const float*)d_in[8];
    const float* b4  = (const float*)d_in[9];

    bf16* adj_hi = (bf16*)symaddr(g_adj_hi);
    bf16* adj_lo = (bf16*)symaddr(g_adj_lo);
    bf16* x_hi   = (bf16*)symaddr(g_x_hi);
    bf16* x_lo   = (bf16*)symaddr(g_x_lo);
    bf16* hA_hi  = (bf16*)symaddr(g_hA_hi);
    bf16* hA_lo  = (bf16*)symaddr(g_hA_lo);
    bf16* hB_hi  = (bf16*)symaddr(g_hB_hi);
    bf16* hB_lo  = (bf16*)symaddr(g_hB_lo);
    bf16* yt_hi  = (bf16*)symaddr(g_yt_hi);
    bf16* yt_lo  = (bf16*)symaddr(g_yt_lo);
    bf16* wt_hi  = (bf16*)symaddr(g_wt_hi);
    bf16* wt_lo  = (bf16*)symaddr(g_wt_lo);
    float* z     = (float*)symaddr(g_z);
    float* part  = (float*)symaddr(g_part);

    cudaFuncSetAttribute(k_gemm, cudaFuncAttributeMaxDynamicSharedMemorySize, SMEM_BYTES);

    const dim3 gAgg(1, 128, 9), gLin(1, 128, 1);

    // 1: x split
    k_xcat<<<2048, 256>>>((const float4*)x, x_hi, x_lo);
    // 2: W1^T [128][512]
    k_tsplit<<<dim3(4, 16), dim3(32, 8)>>>(W1, 512, 128, wt_hi, wt_lo);
    // 3: y1 = x @ W1_bot  -> yt   (B = W1^T cols k=256..511)
    k_gemm<<<gLin, 128, SMEM_BYTES>>>(x_hi, x_lo, 256, wt_hi + 256, wt_lo + 256, 512,
        256, 6, 128, nullptr, nullptr, nullptr, nullptr, 0, yt_hi, yt_lo, nullptr);
    // 4: adj split  [profiled launch]
    k_split<<<4096, 256>>>((const uint4*)adj, (uint4*)adj_hi, (uint4*)adj_lo,
                           (size_t)NN * NN / 8);
    // 5: z1 = adj @ y1 (partials)
    k_gemm<<<gAgg, 128, SMEM_BYTES>>>(adj_hi, adj_lo, NN, yt_hi, yt_lo, NN,
        NN, 3, 128, nullptr, nullptr, nullptr, nullptr, 0, nullptr, nullptr, part);
    // 6: reduce
    k_reducef<<<1024, 256>>>((const float4*)part, 9, (float4*)z);
    // 7-9: remaining weight transposes
    k_tsplit<<<dim3(4, 8), dim3(32, 8)>>>(W2, 256, 128, wt_hi + 65536,  wt_lo + 65536);
    k_tsplit<<<dim3(4, 8), dim3(32, 8)>>>(W3, 256, 128, wt_hi + 98304,  wt_lo + 98304);
    k_tsplit<<<dim3(2, 8), dim3(32, 8)>>>(W4, 256, 64,  wt_hi + 131072, wt_lo + 131072);
    // 10: h2 = relu(x @ W1_top + z + b1) -> hA
    k_gemm<<<gLin, 128, SMEM_BYTES>>>(x_hi, x_lo, 256, wt_hi, wt_lo, 512,
        256, 4, 128, b1, z, hA_hi, hA_lo, 128, nullptr, nullptr, nullptr);

    // ---- layer 2 ----
    k_gemm<<<gLin, 128, SMEM_BYTES>>>(hA_hi, hA_lo, 128,
        wt_hi + 65536 + 128, wt_lo + 65536 + 128, 256,
        128, 6, 128, nullptr, nullptr, nullptr, nullptr, 0, yt_hi, yt_lo, nullptr);
    k_gemm<<<gAgg, 128, SMEM_BYTES>>>(adj_hi, adj_lo, NN, yt_hi, yt_lo, NN,
        NN, 3, 128, nullptr, nullptr, nullptr, nullptr, 0, nullptr, nullptr, part);
    k_reducef<<<1024, 256>>>((const float4*)part, 9, (float4*)z);
    k_gemm<<<gLin, 128, SMEM_BYTES>>>(hA_hi, hA_lo, 128,
        wt_hi + 65536, wt_lo + 65536, 256,
        128, 4, 128, b2, z, hB_hi, hB_lo, 128, nullptr, nullptr, nullptr);

    // ---- layer 3 ----
    k_gemm<<<gLin, 128, SMEM_BYTES>>>(hB_hi, hB_lo, 128,
        wt_hi + 98304 + 128, wt_lo + 98304 + 128, 256,
        128, 6, 128, nullptr, nullptr, nullptr, nullptr, 0, yt_hi, yt_lo, nullptr);
    k_gemm<<<gAgg, 128, SMEM_BYTES>>>(adj_hi, adj_lo, NN, yt_hi, yt_lo, NN,
        NN, 3, 128, nullptr, nullptr, nullptr, nullptr, 0, nullptr, nullptr, part);
    k_reducef<<<1024, 256>>>((const float4*)part, 9, (float4*)z);
    k_gemm<<<gLin, 128, SMEM_BYTES>>>(hB_hi, hB_lo, 128,
        wt_hi + 98304, wt_lo + 98304, 256,
        128, 4, 128, b3, z, hA_hi, hA_lo, 128, nullptr, nullptr, nullptr);

    // ---- layer 4 (N=64; W4^T rows 64..127 are zero -> y/z cols 64..127 zero) ----
    k_gemm<<<gLin, 128, SMEM_BYTES>>>(hA_hi, hA_lo, 128,
        wt_hi + 131072 + 128, wt_lo + 131072 + 128, 256,
        128, 6, 128, nullptr, nullptr, nullptr, nullptr, 0, yt_hi, yt_lo, nullptr);
    k_gemm<<<gAgg, 128, SMEM_BYTES>>>(adj_hi, adj_lo, NN, yt_hi, yt_lo, NN,
        NN, 3, 128, nullptr, nullptr, nullptr, nullptr, 0, nullptr, nullptr, part);
    k_reducef<<<1024, 256>>>((const float4*)part, 9, (float4*)z);
    k_gemm<<<gLin, 128, SMEM_BYTES>>>(hA_hi, hA_lo, 128,
        wt_hi + 131072, wt_lo + 131072, 256,
        128, 5, 64, b4, z, nullptr, nullptr, 0, nullptr, nullptr, (float*)d_out);
}

// round 12
// speedup vs baseline: 1.5136x; 1.2833x over previous
#include <cuda_runtime.h>
#include <cuda_bf16.h>
#include <cuda_fp16.h>
#include <cstdint>
#include <cstddef>

typedef __nv_bfloat16 bf16;

#define NN 8192
#define ADJ_SCALE 4096.0f
#define ADJ_ISCALE (1.0f / 4096.0f)

// ---------------- device scratch (no allocs; zero-init at load) ----------------
__device__ __align__(1024) __half g_adj_hi[(size_t)NN * NN];  // adj*4096 fp16 split
__device__ __align__(1024) __half g_adj_lo[(size_t)NN * NN];
__device__ __align__(1024) bf16 g_x_hi[NN * 256];             // x split, ld 256
__device__ __align__(1024) bf16 g_x_lo[NN * 256];
__device__ __align__(1024) bf16 g_hA_hi[NN * 128];            // layer outputs ping-pong
__device__ __align__(1024) bf16 g_hA_lo[NN * 128];
__device__ __align__(1024) bf16 g_hB_hi[NN * 128];
__device__ __align__(1024) bf16 g_hB_lo[NN * 128];
__device__ __align__(1024) __half g_yt[128 * NN];             // y^T fp16 [128][NN]
__device__ __align__(1024) bf16 g_wt_hi[163840];              // W^T; L4 zero-padded
__device__ __align__(1024) bf16 g_wt_lo[163840];
__device__ __align__(1024) float g_z[NN * 128];               // reduced aggregation
__device__ __align__(1024) float g_part[9 * NN * 128];        // split-K partials

// ---------------- helpers ----------------
__device__ __forceinline__ uint32_t s2u(const void* p) {
    uint32_t a;
    asm("{ .reg .u64 t; cvta.to.shared.u64 t, %1; cvt.u32.u64 %0, t; }" : "=r"(a) : "l"(p));
    return a;
}

#define CP16(dst_u32, src_ptr) \
    asm volatile("cp.async.cg.shared.global [%0], [%1], 16;" :: "r"(dst_u32), "l"(src_ptr) : "memory")

__device__ __forceinline__ void ldsm4(uint32_t a[4], uint32_t addr) {
    asm volatile("ldmatrix.sync.aligned.m8n8.x4.shared.b16 {%0,%1,%2,%3}, [%4];"
                 : "=r"(a[0]), "=r"(a[1]), "=r"(a[2]), "=r"(a[3]) : "r"(addr));
}

__device__ __forceinline__ void mma_bf16(float c[4], const uint32_t a[4], const uint32_t b[2]) {
    asm volatile(
        "mma.sync.aligned.m16n8k16.row.col.f32.bf16.bf16.f32 "
        "{%0,%1,%2,%3}, {%4,%5,%6,%7}, {%8,%9}, {%0,%1,%2,%3};"
        : "+f"(c[0]), "+f"(c[1]), "+f"(c[2]), "+f"(c[3])
        : "r"(a[0]), "r"(a[1]), "r"(a[2]), "r"(a[3]), "r"(b[0]), "r"(b[1]));
}

__device__ __forceinline__ void mma_f16(float c[4], const uint32_t a[4], const uint32_t b[2]) {
    asm volatile(
        "mma.sync.aligned.m16n8k16.row.col.f32.f16.f16.f32 "
        "{%0,%1,%2,%3}, {%4,%5,%6,%7}, {%8,%9}, {%0,%1,%2,%3};"
        : "+f"(c[0]), "+f"(c[1]), "+f"(c[2]), "+f"(c[3])
        : "r"(a[0]), "r"(a[1]), "r"(a[2]), "r"(a[3]), "r"(b[0]), "r"(b[1]));
}

__device__ __forceinline__ void split2(float v, bf16& h, bf16& l) {
    h = __float2bfloat16(v);
    l = __float2bfloat16(v - __bfloat162float(h));
}

// ---------------- prep kernels ----------------
// adj fp32 -> (adj*4096) fp16 hi/lo rounding split; streaming
__global__ void k_split(const float4* __restrict__ src, uint4* __restrict__ hi,
                        uint4* __restrict__ lo, size_t n8) {
    size_t i = (size_t)blockIdx.x * blockDim.x + threadIdx.x;
    size_t stride = (size_t)gridDim.x * blockDim.x;
    for (; i < n8; i += stride) {
        float4 a = __ldcs(src + 2 * i);
        float4 b = __ldcs(src + 2 * i + 1);
        float f[8] = {a.x, a.y, a.z, a.w, b.x, b.y, b.z, b.w};
        __half hh[8], ll[8];
        #pragma unroll
        for (int j = 0; j < 8; ++j) {
            float s = f[j] * ADJ_SCALE;
            __half h = __float2half_rn(s);
            hh[j] = h;
            ll[j] = __float2half_rn(s - __half2float(h));
        }
        uint4 H, L;
        __half2* Hp = (__half2*)&H;
        __half2* Lp = (__half2*)&L;
        #pragma unroll
        for (int q = 0; q < 4; ++q) {
            Hp[q] = __halves2half2(hh[2 * q], hh[2 * q + 1]);
            Lp[q] = __halves2half2(ll[2 * q], ll[2 * q + 1]);
        }
        __stcs(hi + i, H);
        __stcs(lo + i, L);
    }
}

// x [8192,256] fp32 -> split row-major ld 256
__global__ void k_xcat(const float4* __restrict__ x4, bf16* __restrict__ hi,
                       bf16* __restrict__ lo) {
    int idx = blockIdx.x * blockDim.x + threadIdx.x;  // 8192*64
    float4 v = x4[idx];
    size_t base = (size_t)idx * 4;
    bf16 h0, h1, h2, h3, l0, l1, l2, l3;
    split2(v.x, h0, l0); split2(v.y, h1, l1);
    split2(v.z, h2, l2); split2(v.w, h3, l3);
    __nv_bfloat162* H = (__nv_bfloat162*)(hi + base);
    __nv_bfloat162* L = (__nv_bfloat162*)(lo + base);
    H[0] = __halves2bfloat162(h0, h1); H[1] = __halves2bfloat162(h2, h3);
    L[0] = __halves2bfloat162(l0, l1); L[1] = __halves2bfloat162(l2, l3);
}

// transpose + split: src [R, C] fp32 -> dst[c][r] split bf16 (dst ld = R)
__global__ void k_tsplit(const float* __restrict__ src, int R, int C,
                         bf16* __restrict__ dhi, bf16* __restrict__ dlo) {
    __shared__ float t[32][33];
    int bx = blockIdx.x * 32;
    int by = blockIdx.y * 32;
    int tx = threadIdx.x, ty = threadIdx.y;
    #pragma unroll
    for (int i = 0; i < 4; i++)
        t[ty + 8 * i][tx] = src[(size_t)(by + ty + 8 * i) * C + bx + tx];
    __syncthreads();
    #pragma unroll
    for (int i = 0; i < 4; i++) {
        int c = bx + ty + 8 * i;
        float v = t[tx][ty + 8 * i];
        bf16 h, l; split2(v, h, l);
        dhi[(size_t)c * R + by + tx] = h;
        dlo[(size_t)c * R + by + tx] = l;
    }
}

// sum nparts fp32 partials, unscale -> fp32 z
__global__ void k_reducef(const float4* __restrict__ p, int nparts,
                          float4* __restrict__ z) {
    int idx = blockIdx.x * blockDim.x + threadIdx.x;   // NN*128/4
    float4 s = p[idx];
    #pragma unroll 8
    for (int q = 1; q < nparts; ++q) {
        float4 t = p[idx + (size_t)q * (NN * 128 / 4)];
        s.x += t.x; s.y += t.y; s.z += t.z; s.w += t.w;
    }
    s.x *= ADJ_ISCALE; s.y *= ADJ_ISCALE; s.z *= ADJ_ISCALE; s.w *= ADJ_ISCALE;
    z[idx] = s;
}

// ---------------- HMMA GEMM ----------------
// PREC=0: bf16 3-product, A/B split pairs. Stage 48KB: Ah@0,Al@8K,Bh@16K,Bl@32K
// PREC=1: fp16 2-product, A split pair, B single. Stage 32KB: Ah@0,Al@8K,Bh@16K
// 128 threads, 4 warps (2m x 2n), BM=64, BN=128, 2 stages, 2 CTAs/SM.
// mode 3: raw fp32 partials -> of + z*NN*Ncols
// mode 4: relu(v + z + bias) -> split bf16 orm (ld_rm)
// mode 5: v + z + bias -> fp32 of (ld Ncols), guard c < Ncols
// mode 6: v -> transposed fp16 yt (ld NN)
struct Frags {
    uint32_t ah[2][4], al[2][4], bh[4][4], bl[4][4];
};

template <int PREC>
__device__ __forceinline__ void load_stage(
    uint32_t sb, int stage, int kc,
    const void* Ah, const void* Al, int lda,
    const void* Bh, const void* Bl, int ldb,
    int m0, int n0, int tid) {
    const uint32_t SBY = PREC ? 32768u : 49152u;
    uint32_t st = sb + (uint32_t)stage * SBY;
    #pragma unroll
    for (int i = 0; i < 8; ++i) {           // A: 1024 x 16B (hi+lo)
        int g = tid + (i << 7);
        int sub = g >> 9;
        int idx = g & 511;
        int row = idx >> 3;
        int cb = (idx & 7) << 4;
        uint32_t dst = st + (uint32_t)(sub * 8192) + (uint32_t)(row * 128)
                     + (uint32_t)(cb ^ ((row & 7) << 4));
        const char* srcb = (const char*)(sub ? Al : Ah);
        CP16(dst, srcb + 2 * ((size_t)(m0 + row) * lda + kc) + cb);
    }
    if (PREC) {
        #pragma unroll
        for (int i = 0; i < 8; ++i) {       // B: 1024 x 16B single fp16
            int g = tid + (i << 7);
            int row = g >> 3;
            int cb = (g & 7) << 4;
            uint32_t dst = st + 16384u + (uint32_t)(row * 128)
                         + (uint32_t)(cb ^ ((row & 7) << 4));
            CP16(dst, (const char*)Bh + 2 * ((size_t)(n0 + row) * ldb + kc) + cb);
        }
    } else {
        #pragma unroll
        for (int i = 0; i < 16; ++i) {      // B: 2048 x 16B (hi+lo)
            int g = tid + (i << 7);
            int sub = g >> 10;
            int idx = g & 1023;
            int row = idx >> 3;
            int cb = (idx & 7) << 4;
            uint32_t dst = st + 16384u + (uint32_t)(sub * 16384) + (uint32_t)(row * 128)
                         + (uint32_t)(cb ^ ((row & 7) << 4));
            const char* srcb = (const char*)(sub ? Bl : Bh);
            CP16(dst, srcb + 2 * ((size_t)(n0 + row) * ldb + kc) + cb);
        }
    }
}

template <int PREC>
__device__ __forceinline__ void frag_load(uint32_t aB, uint32_t bB, int kq,
                                          uint32_t acol, uint32_t axr,
                                          uint32_t bcol, uint32_t bxr, Frags& f) {
    uint32_t ac = ((uint32_t)(kq * 32) + acol) ^ axr;
    uint32_t bc = ((uint32_t)(kq * 32) + bcol) ^ bxr;
    #pragma unroll
    for (int mi = 0; mi < 2; ++mi) {
        ldsm4(f.ah[mi], aB + (uint32_t)(mi * 2048) + ac);
        ldsm4(f.al[mi], aB + 8192u + (uint32_t)(mi * 2048) + ac);
    }
    #pragma unroll
    for (int j = 0; j < 4; ++j) {
        ldsm4(f.bh[j], bB + (uint32_t)(j * 2048) + bc);
        if (!PREC) ldsm4(f.bl[j], bB + 16384u + (uint32_t)(j * 2048) + bc);
    }
}

template <int PREC>
__device__ __forceinline__ void frag_mma(float acc[2][8][4], const Frags& f) {
    if (PREC) {
        #pragma unroll
        for (int mi = 0; mi < 2; ++mi)
            #pragma unroll
            for (int ni = 0; ni < 8; ++ni)
                mma_f16(acc[mi][ni], f.ah[mi], &f.bh[ni >> 1][(ni & 1) * 2]);
        #pragma unroll
        for (int mi = 0; mi < 2; ++mi)
            #pragma unroll
            for (int ni = 0; ni < 8; ++ni)
                mma_f16(acc[mi][ni], f.al[mi], &f.bh[ni >> 1][(ni & 1) * 2]);
    } else {
        #pragma unroll
        for (int mi = 0; mi < 2; ++mi)
            #pragma unroll
            for (int ni = 0; ni < 8; ++ni)
                mma_bf16(acc[mi][ni], f.ah[mi], &f.bh[ni >> 1][(ni & 1) * 2]);
        #pragma unroll
        for (int mi = 0; mi < 2; ++mi)
            #pragma unroll
            for (int ni = 0; ni < 8; ++ni)
                mma_bf16(acc[mi][ni], f.ah[mi], &f.bl[ni >> 1][(ni & 1) * 2]);
        #pragma unroll
        for (int mi = 0; mi < 2; ++mi)
            #pragma unroll
            for (int ni = 0; ni < 8; ++ni)
                mma_bf16(acc[mi][ni], f.al[mi], &f.bh[ni >> 1][(ni & 1) * 2]);
    }
}

template <int PREC>
__global__ void __launch_bounds__(128, 2)
k_gemm(const void* __restrict__ Ah, const void* __restrict__ Al, int lda,
       const void* __restrict__ Bh, const void* __restrict__ Bl, int ldb,
       int K, int mode, int Ncols, const float* __restrict__ bias,
       const float* __restrict__ zin,
       bf16* __restrict__ orm_hi, bf16* __restrict__ orm_lo, int ld_rm,
       __half* __restrict__ yt,
       float* __restrict__ of) {
    extern __shared__ char smem[];
    const int tid = threadIdx.x;
    const uint32_t sb = s2u(smem);
    const uint32_t SBY = PREC ? 32768u : 49152u;
    const int m0 = (int)blockIdx.y * 64;
    const int n0 = (int)blockIdx.x * 128;
    const int CT = K >> 6;
    const int nz = (int)gridDim.z;
    const int c0 = (int)((size_t)blockIdx.z * CT / nz);
    const int c1 = (int)(((size_t)blockIdx.z + 1) * CT / nz);
    const int lane = tid & 31, wid = tid >> 5;
    const int wm = wid >> 1, wn = wid & 1;
    const int lg = lane >> 3, lr = lane & 7;

    const int arow = wm * 32 + (lg & 1) * 8 + lr;
    const uint32_t acol = (uint32_t)((lg >> 1) * 16);
    const uint32_t axr = (uint32_t)((arow & 7) << 4);
    const int brow = wn * 64 + (lg >> 1) * 8 + lr;
    const uint32_t bcol = (uint32_t)((lg & 1) * 16);
    const uint32_t bxr = (uint32_t)((brow & 7) << 4);

    float acc[2][8][4] = {};

    load_stage<PREC>(sb, 0, c0 << 6, Ah, Al, lda, Bh, Bl, ldb, m0, n0, tid);
    asm volatile("cp.async.commit_group;" ::: "memory");
    load_stage<PREC>(sb, 1, (c0 + 1) << 6, Ah, Al, lda, Bh, Bl, ldb, m0, n0, tid);
    asm volatile("cp.async.commit_group;" ::: "memory");

    for (int c = c0; c < c1; ++c) {
        asm volatile("cp.async.wait_group 1;" ::: "memory");
        __syncthreads();

        uint32_t st = sb + (uint32_t)(((c - c0) & 1) * SBY);
        uint32_t aB = st + (uint32_t)(arow * 128);
        uint32_t bB = st + 16384u + (uint32_t)(brow * 128);

        Frags f;
        #pragma unroll
        for (int kq = 0; kq < 3; ++kq) {
            frag_load<PREC>(aB, bB, kq, acol, axr, bcol, bxr, f);
            frag_mma<PREC>(acc, f);
        }
        frag_load<PREC>(aB, bB, 3, acol, axr, bcol, bxr, f);
        __syncthreads();
        int nc = c + 2;
        if (nc < c1)
            load_stage<PREC>(sb, (c - c0) & 1, nc << 6, Ah, Al, lda, Bh, Bl, ldb, m0, n0, tid);
        asm volatile("cp.async.commit_group;" ::: "memory");
        frag_mma<PREC>(acc, f);
    }

    // ---------------- epilogue ----------------
    if (mode == 3) of += (size_t)blockIdx.z * NN * Ncols;
    #pragma unroll
    for (int mi = 0; mi < 2; ++mi) {
        int r0 = m0 + wm * 32 + mi * 16 + (lane >> 2);
        #pragma unroll
        for (int ni = 0; ni < 8; ++ni) {
            int c = n0 + wn * 64 + ni * 8 + ((lane & 3) << 1);
            float v0 = acc[mi][ni][0], v1 = acc[mi][ni][1];
            float v2 = acc[mi][ni][2], v3 = acc[mi][ni][3];
            if (mode == 3) {
                *(float2*)(of + (size_t)r0 * Ncols + c)       = make_float2(v0, v1);
                *(float2*)(of + (size_t)(r0 + 8) * Ncols + c) = make_float2(v2, v3);
            } else if (mode == 6) {
                yt[(size_t)c * NN + r0]           = __float2half_rn(v0);
                yt[(size_t)(c + 1) * NN + r0]     = __float2half_rn(v1);
                yt[(size_t)c * NN + r0 + 8]       = __float2half_rn(v2);
                yt[(size_t)(c + 1) * NN + r0 + 8] = __float2half_rn(v3);
            } else {
                float b0v = bias[c], b1v = bias[c + 1];
                float2 za = *(const float2*)(zin + (size_t)r0 * 128 + c);
                float2 zb = *(const float2*)(zin + (size_t)(r0 + 8) * 128 + c);
                v0 += za.x + b0v; v1 += za.y + b1v;
                v2 += zb.x + b0v; v3 += zb.y + b1v;
                if (mode == 5) {
                    if (c < Ncols) {
                        *(float2*)(of + (size_t)r0 * Ncols + c)       = make_float2(v0, v1);
                        *(float2*)(of + (size_t)(r0 + 8) * Ncols + c) = make_float2(v2, v3);
                    }
                } else {  // mode 4
                    v0 = fmaxf(v0, 0.f); v1 = fmaxf(v1, 0.f);
                    v2 = fmaxf(v2, 0.f); v3 = fmaxf(v3, 0.f);
                    bf16 h0, l0, h1, l1, h2, l2, h3, l3;
                    split2(v0, h0, l0); split2(v1, h1, l1);
                    split2(v2, h2, l2); split2(v3, h3, l3);
                    *(__nv_bfloat162*)(orm_hi + (size_t)r0 * ld_rm + c) = __halves2bfloat162(h0, h1);
                    *(__nv_bfloat162*)(orm_lo + (size_t)r0 * ld_rm + c) = __halves2bfloat162(l0, l1);
                    *(__nv_bfloat162*)(orm_hi + (size_t)(r0 + 8) * ld_rm + c) = __halves2bfloat162(h2, h3);
                    *(__nv_bfloat162*)(orm_lo + (size_t)(r0 + 8) * ld_rm + c) = __halves2bfloat162(l2, l3);
                }
            }
        }
    }
}

// ---------------- host ----------------
static void* symaddr(const void* sym) {
    void* p = nullptr;
    cudaGetSymbolAddress(&p, sym);
    return p;
}

extern "C" void kernel_launch(void* const* d_in, const int* in_sizes, int n_in,
                              void* d_out, int out_size) {
    (void)in_sizes; (void)n_in; (void)out_size;
    const float* x   = (const float*)d_in[0];
    const float* adj = (const float*)d_in[1];
    const float* W1  = (const float*)d_in[2];
    const float* b1  = (const float*)d_in[3];
    const float* W2  = (const float*)d_in[4];
    const float* b2  = (const float*)d_in[5];
    const float* W3  = (const float*)d_in[6];
    const float* b3  = (const float*)d_in[7];
    const float* W4  = (const float*)d_in[8];
    const float* b4  = (const float*)d_in[9];

    __half* adj_hi = (__half*)symaddr(g_adj_hi);
    __half* adj_lo = (__half*)symaddr(g_adj_lo);
    bf16* x_hi   = (bf16*)symaddr(g_x_hi);
    bf16* x_lo   = (bf16*)symaddr(g_x_lo);
    bf16* hA_hi  = (bf16*)symaddr(g_hA_hi);
    bf16* hA_lo  = (bf16*)symaddr(g_hA_lo);
    bf16* hB_hi  = (bf16*)symaddr(g_hB_hi);
    bf16* hB_lo  = (bf16*)symaddr(g_hB_lo);
    __half* yt   = (__half*)symaddr(g_yt);
    bf16* wt_hi  = (bf16*)symaddr(g_wt_hi);
    bf16* wt_lo  = (bf16*)symaddr(g_wt_lo);
    float* z     = (float*)symaddr(g_z);
    float* part  = (float*)symaddr(g_part);

    cudaFuncSetAttribute(k_gemm<0>, cudaFuncAttributeMaxDynamicSharedMemorySize, 98304);
    cudaFuncSetAttribute(k_gemm<1>, cudaFuncAttributeMaxDynamicSharedMemorySize, 65536);

    const dim3 gAgg(1, 128, 9), gLin(1, 128, 1);

    // prep
    k_xcat<<<2048, 256>>>((const float4*)x, x_hi, x_lo);
    k_tsplit<<<dim3(4, 16), dim3(32, 8)>>>(W1, 512, 128, wt_hi, wt_lo);
    // y1 = x @ W1_bot -> yt fp16
    k_gemm<0><<<gLin, 128, 98304>>>(x_hi, x_lo, 256, wt_hi + 256, wt_lo + 256, 512,
        256, 6, 128, nullptr, nullptr, nullptr, nullptr, 0, yt, nullptr);
    // adj fp16 split
    k_split<<<4096, 256>>>((const float4*)adj, (uint4*)adj_hi, (uint4*)adj_lo,
                           (size_t)NN * NN / 8);
    // z1 = adj @ y1 (fp16 2-product)
    k_gemm<1><<<gAgg, 128, 65536>>>(adj_hi, adj_lo, NN, yt, nullptr, NN,
        NN, 3, 128, nullptr, nullptr, nullptr, nullptr, 0, nullptr, part);
    k_reducef<<<1024, 256>>>((const float4*)part, 9, (float4*)z);
    k_tsplit<<<dim3(4, 8), dim3(32, 8)>>>(W2, 256, 128, wt_hi + 65536,  wt_lo + 65536);
    k_tsplit<<<dim3(4, 8), dim3(32, 8)>>>(W3, 256, 128, wt_hi + 98304,  wt_lo + 98304);
    k_tsplit<<<dim3(2, 8), dim3(32, 8)>>>(W4, 256, 64,  wt_hi + 131072, wt_lo + 131072);
    // h2 = relu(x @ W1_top + z + b1) -> hA
    k_gemm<0><<<gLin, 128, 98304>>>(x_hi, x_lo, 256, wt_hi, wt_lo, 512,
        256, 4, 128, b1, z, hA_hi, hA_lo, 128, nullptr, nullptr);

    // ---- layer 2 ----
    k_gemm<0><<<gLin, 128, 98304>>>(hA_hi, hA_lo, 128,
        wt_hi + 65536 + 128, wt_lo + 65536 + 128, 256,
        128, 6, 128, nullptr, nullptr, nullptr, nullptr, 0, yt, nullptr);
    k_gemm<1><<<gAgg, 128, 65536>>>(adj_hi, adj_lo, NN, yt, nullptr, NN,
        NN, 3, 128, nullptr, nullptr, nullptr, nullptr, 0, nullptr, part);
    k_reducef<<<1024, 256>>>((const float4*)part, 9, (float4*)z);
    k_gemm<0><<<gLin, 128, 98304>>>(hA_hi, hA_lo, 128,
        wt_hi + 65536, wt_lo + 65536, 256,
        128, 4, 128, b2, z, hB_hi, hB_lo, 128, nullptr, nullptr);

    // ---- layer 3 ----
    k_gemm<0><<<gLin, 128, 98304>>>(hB_hi, hB_lo, 128,
        wt_hi + 98304 + 128, wt_lo + 98304 + 128, 256,
        128, 6, 128, nullptr, nullptr, nullptr, nullptr, 0, yt, nullptr);
    k_gemm<1><<<gAgg, 128, 65536>>>(adj_hi, adj_lo, NN, yt, nullptr, NN,
        NN, 3, 128, nullptr, nullptr, nullptr, nullptr, 0, nullptr, part);
    k_reducef<<<1024, 256>>>((const float4*)part, 9, (float4*)z);
    k_gemm<0><<<gLin, 128, 98304>>>(hB_hi, hB_lo, 128,
        wt_hi + 98304, wt_lo + 98304, 256,
        128, 4, 128, b3, z, hA_hi, hA_lo, 128, nullptr, nullptr);

    // ---- layer 4 (N=64; W4^T rows 64..127 zero -> y/z cols 64..127 zero) ----
    k_gemm<0><<<gLin, 128, 98304>>>(hA_hi, hA_lo, 128,
        wt_hi + 131072 + 128, wt_lo + 131072 + 128, 256,
        128, 6, 128, nullptr, nullptr, nullptr, nullptr, 0, yt, nullptr);
    k_gemm<1><<<gAgg, 128, 65536>>>(adj_hi, adj_lo, NN, yt, nullptr, NN,
        NN, 3, 128, nullptr, nullptr, nullptr, nullptr, 0, nullptr, part);
    k_reducef<<<1024, 256>>>((const float4*)part, 9, (float4*)z);
    k_gemm<0><<<gLin, 128, 98304>>>(hA_hi, hA_lo, 128,
        wt_hi + 131072, wt_lo + 131072, 256,
        128, 5, 64, b4, z, nullptr, nullptr, 0, nullptr, (float*)d_out);
}

// round 13
// speedup vs baseline: 2.1835x; 1.4426x over previous
#include <cuda_runtime.h>
#include <cuda_bf16.h>
#include <cuda_fp16.h>
#include <cstdint>
#include <cstddef>

typedef __nv_bfloat16 bf16;

#define NN 8192
#define ADJ_SCALE 4096.0f
#define ADJ_ISCALE (1.0f / 4096.0f)
#define NZ_AGG 10

// ---------------- device scratch (no allocs; zero-init at load) ----------------
__device__ __align__(1024) __half g_adj[(size_t)NN * NN];     // adj*4096 fp16
__device__ __align__(1024) bf16 g_x_hi[NN * 256];             // x split, ld 256
__device__ __align__(1024) bf16 g_x_lo[NN * 256];
__device__ __align__(1024) bf16 g_hA_hi[NN * 128];            // layer outputs ping-pong
__device__ __align__(1024) bf16 g_hA_lo[NN * 128];
__device__ __align__(1024) bf16 g_hB_hi[NN * 128];
__device__ __align__(1024) bf16 g_hB_lo[NN * 128];
__device__ __align__(1024) __half g_yt[128 * NN];             // y^T fp16 [128][NN]
__device__ __align__(1024) bf16 g_wt_hi[163840];              // W^T; L4 zero-padded
__device__ __align__(1024) bf16 g_wt_lo[163840];
__device__ __align__(1024) float g_z[NN * 128];               // reduced aggregation
__device__ __align__(1024) float g_part[NZ_AGG * NN * 128];   // split-K partials

// ---------------- helpers ----------------
__device__ __forceinline__ uint32_t s2u(const void* p) {
    uint32_t a;
    asm("{ .reg .u64 t; cvta.to.shared.u64 t, %1; cvt.u32.u64 %0, t; }" : "=r"(a) : "l"(p));
    return a;
}

#define CP16(dst_u32, src_ptr) \
    asm volatile("cp.async.cg.shared.global [%0], [%1], 16;" :: "r"(dst_u32), "l"(src_ptr) : "memory")

__device__ __forceinline__ void ldsm4(uint32_t a[4], uint32_t addr) {
    asm volatile("ldmatrix.sync.aligned.m8n8.x4.shared.b16 {%0,%1,%2,%3}, [%4];"
                 : "=r"(a[0]), "=r"(a[1]), "=r"(a[2]), "=r"(a[3]) : "r"(addr));
}

__device__ __forceinline__ void mma_bf16(float c[4], const uint32_t a[4], const uint32_t b[2]) {
    asm volatile(
        "mma.sync.aligned.m16n8k16.row.col.f32.bf16.bf16.f32 "
        "{%0,%1,%2,%3}, {%4,%5,%6,%7}, {%8,%9}, {%0,%1,%2,%3};"
        : "+f"(c[0]), "+f"(c[1]), "+f"(c[2]), "+f"(c[3])
        : "r"(a[0]), "r"(a[1]), "r"(a[2]), "r"(a[3]), "r"(b[0]), "r"(b[1]));
}

__device__ __forceinline__ void mma_f16(float c[4], const uint32_t a[4], const uint32_t b[2]) {
    asm volatile(
        "mma.sync.aligned.m16n8k16.row.col.f32.f16.f16.f32 "
        "{%0,%1,%2,%3}, {%4,%5,%6,%7}, {%8,%9}, {%0,%1,%2,%3};"
        : "+f"(c[0]), "+f"(c[1]), "+f"(c[2]), "+f"(c[3])
        : "r"(a[0]), "r"(a[1]), "r"(a[2]), "r"(a[3]), "r"(b[0]), "r"(b[1]));
}

__device__ __forceinline__ void split2(float v, bf16& h, bf16& l) {
    h = __float2bfloat16(v);
    l = __float2bfloat16(v - __bfloat162float(h));
}

// ---------------- prep kernels ----------------
// adj fp32 -> (adj*4096) single fp16; streaming
__global__ void k_split(const float4* __restrict__ src, uint4* __restrict__ dst,
                        size_t n8) {
    size_t i = (size_t)blockIdx.x * blockDim.x + threadIdx.x;
    size_t stride = (size_t)gridDim.x * blockDim.x;
    for (; i < n8; i += stride) {
        float4 a = __ldcs(src + 2 * i);
        float4 b = __ldcs(src + 2 * i + 1);
        uint4 H;
        __half2* Hp = (__half2*)&H;
        Hp[0] = __floats2half2_rn(a.x * ADJ_SCALE, a.y * ADJ_SCALE);
        Hp[1] = __floats2half2_rn(a.z * ADJ_SCALE, a.w * ADJ_SCALE);
        Hp[2] = __floats2half2_rn(b.x * ADJ_SCALE, b.y * ADJ_SCALE);
        Hp[3] = __floats2half2_rn(b.z * ADJ_SCALE, b.w * ADJ_SCALE);
        __stcs(dst + i, H);
    }
}

// x [8192,256] fp32 -> split row-major ld 256
__global__ void k_xcat(const float4* __restrict__ x4, bf16* __restrict__ hi,
                       bf16* __restrict__ lo) {
    int idx = blockIdx.x * blockDim.x + threadIdx.x;  // 8192*64
    float4 v = x4[idx];
    size_t base = (size_t)idx * 4;
    bf16 h0, h1, h2, h3, l0, l1, l2, l3;
    split2(v.x, h0, l0); split2(v.y, h1, l1);
    split2(v.z, h2, l2); split2(v.w, h3, l3);
    __nv_bfloat162* H = (__nv_bfloat162*)(hi + base);
    __nv_bfloat162* L = (__nv_bfloat162*)(lo + base);
    H[0] = __halves2bfloat162(h0, h1); H[1] = __halves2bfloat162(h2, h3);
    L[0] = __halves2bfloat162(l0, l1); L[1] = __halves2bfloat162(l2, l3);
}

// transpose + split: src [R, C] fp32 -> dst[c][r] split bf16 (dst ld = R)
__global__ void k_tsplit(const float* __restrict__ src, int R, int C,
                         bf16* __restrict__ dhi, bf16* __restrict__ dlo) {
    __shared__ float t[32][33];
    int bx = blockIdx.x * 32;
    int by = blockIdx.y * 32;
    int tx = threadIdx.x, ty = threadIdx.y;
    #pragma unroll
    for (int i = 0; i < 4; i++)
        t[ty + 8 * i][tx] = src[(size_t)(by + ty + 8 * i) * C + bx + tx];
    __syncthreads();
    #pragma unroll
    for (int i = 0; i < 4; i++) {
        int c = bx + ty + 8 * i;
        float v = t[tx][ty + 8 * i];
        bf16 h, l; split2(v, h, l);
        dhi[(size_t)c * R + by + tx] = h;
        dlo[(size_t)c * R + by + tx] = l;
    }
}

// sum nparts fp32 partials, unscale -> fp32 z
__global__ void k_reducef(const float4* __restrict__ p, int nparts,
                          float4* __restrict__ z) {
    int idx = blockIdx.x * blockDim.x + threadIdx.x;   // NN*128/4
    float4 s = p[idx];
    #pragma unroll 10
    for (int q = 1; q < nparts; ++q) {
        float4 t = p[idx + (size_t)q * (NN * 128 / 4)];
        s.x += t.x; s.y += t.y; s.z += t.z; s.w += t.w;
    }
    s.x *= ADJ_ISCALE; s.y *= ADJ_ISCALE; s.z *= ADJ_ISCALE; s.w *= ADJ_ISCALE;
    z[idx] = s;
}

// ---------------- fp16 single-product aggregation GEMM ----------------
// partials[z] += A(fp16)[64, K] @ B(fp16)[128, K]^T
// 128 threads, 4 warps (2m x 2n), BM=64, BN=128. Stage 24KB (A@0 8K, B@8K 16K),
// 2 stages, 3 CTAs/SM. Split-K via blockIdx.z (uneven chunk ranges).
#define AGG_STAGE 24576u

__device__ __forceinline__ void agg_load_stage(
    uint32_t sb, int stage, int kc,
    const __half* A, int lda, const __half* B, int ldb,
    int m0, int n0, int tid) {
    uint32_t st = sb + (uint32_t)stage * AGG_STAGE;
    #pragma unroll
    for (int i = 0; i < 4; ++i) {           // A: 512 x 16B
        int g = tid + (i << 7);
        int row = g >> 3;
        int cb = (g & 7) << 4;
        uint32_t dst = st + (uint32_t)(row * 128) + (uint32_t)(cb ^ ((row & 7) << 4));
        CP16(dst, (const char*)(A + (size_t)(m0 + row) * lda + kc) + cb);
    }
    #pragma unroll
    for (int i = 0; i < 8; ++i) {           // B: 1024 x 16B
        int g = tid + (i << 7);
        int row = g >> 3;
        int cb = (g & 7) << 4;
        uint32_t dst = st + 8192u + (uint32_t)(row * 128) + (uint32_t)(cb ^ ((row & 7) << 4));
        CP16(dst, (const char*)(B + (size_t)(n0 + row) * ldb + kc) + cb);
    }
}

struct AggFrags { uint32_t ah[2][4], bh[4][4]; };

__device__ __forceinline__ void agg_frag_load(uint32_t aB, uint32_t bB, int kq,
                                              uint32_t acol, uint32_t axr,
                                              uint32_t bcol, uint32_t bxr, AggFrags& f) {
    uint32_t ac = ((uint32_t)(kq * 32) + acol) ^ axr;
    uint32_t bc = ((uint32_t)(kq * 32) + bcol) ^ bxr;
    #pragma unroll
    for (int mi = 0; mi < 2; ++mi)
        ldsm4(f.ah[mi], aB + (uint32_t)(mi * 2048) + ac);
    #pragma unroll
    for (int j = 0; j < 4; ++j)
        ldsm4(f.bh[j], bB + (uint32_t)(j * 2048) + bc);
}

__device__ __forceinline__ void agg_frag_mma(float acc[2][8][4], const AggFrags& f) {
    #pragma unroll
    for (int mi = 0; mi < 2; ++mi)
        #pragma unroll
        for (int ni = 0; ni < 8; ++ni)
            mma_f16(acc[mi][ni], f.ah[mi], &f.bh[ni >> 1][(ni & 1) * 2]);
}

__global__ void __launch_bounds__(128, 3)
k_agg(const __half* __restrict__ A, int lda, const __half* __restrict__ B, int ldb,
      int K, float* __restrict__ of) {
    extern __shared__ char smem[];
    const int tid = threadIdx.x;
    const uint32_t sb = s2u(smem);
    const int m0 = (int)blockIdx.y * 64;
    const int n0 = (int)blockIdx.x * 128;
    const int CT = K >> 6;
    const int nz = (int)gridDim.z;
    const int c0 = (int)((size_t)blockIdx.z * CT / nz);
    const int c1 = (int)(((size_t)blockIdx.z + 1) * CT / nz);
    const int lane = tid & 31, wid = tid >> 5;
    const int wm = wid >> 1, wn = wid & 1;
    const int lg = lane >> 3, lr = lane & 7;

    const int arow = wm * 32 + (lg & 1) * 8 + lr;
    const uint32_t acol = (uint32_t)((lg >> 1) * 16);
    const uint32_t axr = (uint32_t)((arow & 7) << 4);
    const int brow = wn * 64 + (lg >> 1) * 8 + lr;
    const uint32_t bcol = (uint32_t)((lg & 1) * 16);
    const uint32_t bxr = (uint32_t)((brow & 7) << 4);

    float acc[2][8][4] = {};

    agg_load_stage(sb, 0, c0 << 6, A, lda, B, ldb, m0, n0, tid);
    asm volatile("cp.async.commit_group;" ::: "memory");
    agg_load_stage(sb, 1, (c0 + 1) << 6, A, lda, B, ldb, m0, n0, tid);
    asm volatile("cp.async.commit_group;" ::: "memory");

    for (int c = c0; c < c1; ++c) {
        asm volatile("cp.async.wait_group 1;" ::: "memory");
        __syncthreads();

        uint32_t st = sb + (uint32_t)(((c - c0) & 1) * AGG_STAGE);
        uint32_t aB = st + (uint32_t)(arow * 128);
        uint32_t bB = st + 8192u + (uint32_t)(brow * 128);

        AggFrags f;
        #pragma unroll
        for (int kq = 0; kq < 3; ++kq) {
            agg_frag_load(aB, bB, kq, acol, axr, bcol, bxr, f);
            agg_frag_mma(acc, f);
        }
        agg_frag_load(aB, bB, 3, acol, axr, bcol, bxr, f);
        __syncthreads();
        int nc = c + 2;
        if (nc < c1)
            agg_load_stage(sb, (c - c0) & 1, nc << 6, A, lda, B, ldb, m0, n0, tid);
        asm volatile("cp.async.commit_group;" ::: "memory");
        agg_frag_mma(acc, f);
    }

    of += (size_t)blockIdx.z * NN * 128;
    #pragma unroll
    for (int mi = 0; mi < 2; ++mi) {
        int r0 = m0 + wm * 32 + mi * 16 + (lane >> 2);
        #pragma unroll
        for (int ni = 0; ni < 8; ++ni) {
            int c = n0 + wn * 64 + ni * 8 + ((lane & 3) << 1);
            *(float2*)(of + (size_t)r0 * 128 + c)       = make_float2(acc[mi][ni][0], acc[mi][ni][1]);
            *(float2*)(of + (size_t)(r0 + 8) * 128 + c) = make_float2(acc[mi][ni][2], acc[mi][ni][3]);
        }
    }
}

// ---------------- bf16 3-product GEMM (linears) ----------------
// 128 threads, BM=64, BN=128, stage 48KB, 2 stages, 2 CTAs/SM.
// mode 4: relu(v + z + bias) -> split bf16 orm (ld_rm)
// mode 5: v + z + bias -> fp32 of (ld Ncols), guard c < Ncols
// mode 6: v -> transposed fp16 yt (ld NN)
#define LIN_STAGE 49152u

__device__ __forceinline__ void lin_load_stage(
    uint32_t sb, int stage, int kc,
    const bf16* Ah, const bf16* Al, int lda,
    const bf16* Bh, const bf16* Bl, int ldb,
    int m0, int n0, int tid) {
    uint32_t st = sb + (uint32_t)stage * LIN_STAGE;
    #pragma unroll
    for (int i = 0; i < 8; ++i) {
        int g = tid + (i << 7);
        int sub = g >> 9;
        int idx = g & 511;
        int row = idx >> 3;
        int cb = (idx & 7) << 4;
        uint32_t dst = st + (uint32_t)(sub * 8192) + (uint32_t)(row * 128)
                     + (uint32_t)(cb ^ ((row & 7) << 4));
        const bf16* srcb = sub ? Al : Ah;
        CP16(dst, (const char*)(srcb + (size_t)(m0 + row) * lda + kc) + cb);
    }
    #pragma unroll
    for (int i = 0; i < 16; ++i) {
        int g = tid + (i << 7);
        int sub = g >> 10;
        int idx = g & 1023;
        int row = idx >> 3;
        int cb = (idx & 7) << 4;
        uint32_t dst = st + 16384u + (uint32_t)(sub * 16384) + (uint32_t)(row * 128)
                     + (uint32_t)(cb ^ ((row & 7) << 4));
        const bf16* srcb = sub ? Bl : Bh;
        CP16(dst, (const char*)(srcb + (size_t)(n0 + row) * ldb + kc) + cb);
    }
}

struct Frags { uint32_t ah[2][4], al[2][4], bh[4][4], bl[4][4]; };

__device__ __forceinline__ void lin_frag_load(uint32_t aB, uint32_t bB, int kq,
                                              uint32_t acol, uint32_t axr,
                                              uint32_t bcol, uint32_t bxr, Frags& f) {
    uint32_t ac = ((uint32_t)(kq * 32) + acol) ^ axr;
    uint32_t bc = ((uint32_t)(kq * 32) + bcol) ^ bxr;
    #pragma unroll
    for (int mi = 0; mi < 2; ++mi) {
        ldsm4(f.ah[mi], aB + (uint32_t)(mi * 2048) + ac);
        ldsm4(f.al[mi], aB + 8192u + (uint32_t)(mi * 2048) + ac);
    }
    #pragma unroll
    for (int j = 0; j < 4; ++j) {
        ldsm4(f.bh[j], bB + (uint32_t)(j * 2048) + bc);
        ldsm4(f.bl[j], bB + 16384u + (uint32_t)(j * 2048) + bc);
    }
}

__device__ __forceinline__ void lin_frag_mma(float acc[2][8][4], const Frags& f) {
    #pragma unroll
    for (int mi = 0; mi < 2; ++mi)
        #pragma unroll
        for (int ni = 0; ni < 8; ++ni)
            mma_bf16(acc[mi][ni], f.ah[mi], &f.bh[ni >> 1][(ni & 1) * 2]);
    #pragma unroll
    for (int mi = 0; mi < 2; ++mi)
        #pragma unroll
        for (int ni = 0; ni < 8; ++ni)
            mma_bf16(acc[mi][ni], f.ah[mi], &f.bl[ni >> 1][(ni & 1) * 2]);
    #pragma unroll
    for (int mi = 0; mi < 2; ++mi)
        #pragma unroll
        for (int ni = 0; ni < 8; ++ni)
            mma_bf16(acc[mi][ni], f.al[mi], &f.bh[ni >> 1][(ni & 1) * 2]);
}

__global__ void __launch_bounds__(128, 2)
k_gemm(const bf16* __restrict__ Ah, const bf16* __restrict__ Al, int lda,
       const bf16* __restrict__ Bh, const bf16* __restrict__ Bl, int ldb,
       int K, int mode, int Ncols, const float* __restrict__ bias,
       const float* __restrict__ zin,
       bf16* __restrict__ orm_hi, bf16* __restrict__ orm_lo, int ld_rm,
       __half* __restrict__ yt,
       float* __restrict__ of) {
    extern __shared__ char smem[];
    const int tid = threadIdx.x;
    const uint32_t sb = s2u(smem);
    const int m0 = (int)blockIdx.y * 64;
    const int n0 = (int)blockIdx.x * 128;
    const int C = K >> 6;
    const int lane = tid & 31, wid = tid >> 5;
    const int wm = wid >> 1, wn = wid & 1;
    const int lg = lane >> 3, lr = lane & 7;

    const int arow = wm * 32 + (lg & 1) * 8 + lr;
    const uint32_t acol = (uint32_t)((lg >> 1) * 16);
    const uint32_t axr = (uint32_t)((arow & 7) << 4);
    const int brow = wn * 64 + (lg >> 1) * 8 + lr;
    const uint32_t bcol = (uint32_t)((lg & 1) * 16);
    const uint32_t bxr = (uint32_t)((brow & 7) << 4);

    float acc[2][8][4] = {};

    lin_load_stage(sb, 0, 0, Ah, Al, lda, Bh, Bl, ldb, m0, n0, tid);
    asm volatile("cp.async.commit_group;" ::: "memory");
    lin_load_stage(sb, 1, 64, Ah, Al, lda, Bh, Bl, ldb, m0, n0, tid);
    asm volatile("cp.async.commit_group;" ::: "memory");

    for (int c = 0; c < C; ++c) {
        asm volatile("cp.async.wait_group 1;" ::: "memory");
        __syncthreads();

        uint32_t st = sb + (uint32_t)((c & 1) * LIN_STAGE);
        uint32_t aB = st + (uint32_t)(arow * 128);
        uint32_t bB = st + 16384u + (uint32_t)(brow * 128);

        Frags f;
        #pragma unroll
        for (int kq = 0; kq < 3; ++kq) {
            lin_frag_load(aB, bB, kq, acol, axr, bcol, bxr, f);
            lin_frag_mma(acc, f);
        }
        lin_frag_load(aB, bB, 3, acol, axr, bcol, bxr, f);
        __syncthreads();
        int nc = c + 2;
        if (nc < C)
            lin_load_stage(sb, c & 1, nc << 6, Ah, Al, lda, Bh, Bl, ldb, m0, n0, tid);
        asm volatile("cp.async.commit_group;" ::: "memory");
        lin_frag_mma(acc, f);
    }

    #pragma unroll
    for (int mi = 0; mi < 2; ++mi) {
        int r0 = m0 + wm * 32 + mi * 16 + (lane >> 2);
        #pragma unroll
        for (int ni = 0; ni < 8; ++ni) {
            int c = n0 + wn * 64 + ni * 8 + ((lane & 3) << 1);
            float v0 = acc[mi][ni][0], v1 = acc[mi][ni][1];
            float v2 = acc[mi][ni][2], v3 = acc[mi][ni][3];
            if (mode == 6) {
                yt[(size_t)c * NN + r0]           = __float2half_rn(v0);
                yt[(size_t)(c + 1) * NN + r0]     = __float2half_rn(v1);
                yt[(size_t)c * NN + r0 + 8]       = __float2half_rn(v2);
                yt[(size_t)(c + 1) * NN + r0 + 8] = __float2half_rn(v3);
            } else {
                float b0v = bias[c], b1v = bias[c + 1];
                float2 za = *(const float2*)(zin + (size_t)r0 * 128 + c);
                float2 zb = *(const float2*)(zin + (size_t)(r0 + 8) * 128 + c);
                v0 += za.x + b0v; v1 += za.y + b1v;
                v2 += zb.x + b0v; v3 += zb.y + b1v;
                if (mode == 5) {
                    if (c < Ncols) {
                        *(float2*)(of + (size_t)r0 * Ncols + c)       = make_float2(v0, v1);
                        *(float2*)(of + (size_t)(r0 + 8) * Ncols + c) = make_float2(v2, v3);
                    }
                } else {  // mode 4
                    v0 = fmaxf(v0, 0.f); v1 = fmaxf(v1, 0.f);
                    v2 = fmaxf(v2, 0.f); v3 = fmaxf(v3, 0.f);
                    bf16 h0, l0, h1, l1, h2, l2, h3, l3;
                    split2(v0, h0, l0); split2(v1, h1, l1);
                    split2(v2, h2, l2); split2(v3, h3, l3);
                    *(__nv_bfloat162*)(orm_hi + (size_t)r0 * ld_rm + c) = __halves2bfloat162(h0, h1);
                    *(__nv_bfloat162*)(orm_lo + (size_t)r0 * ld_rm + c) = __halves2bfloat162(l0, l1);
                    *(__nv_bfloat162*)(orm_hi + (size_t)(r0 + 8) * ld_rm + c) = __halves2bfloat162(h2, h3);
                    *(__nv_bfloat162*)(orm_lo + (size_t)(r0 + 8) * ld_rm + c) = __halves2bfloat162(l2, l3);
                }
            }
        }
    }
}

// ---------------- host ----------------
static void* symaddr(const void* sym) {
    void* p = nullptr;
    cudaGetSymbolAddress(&p, sym);
    return p;
}

extern "C" void kernel_launch(void* const* d_in, const int* in_sizes, int n_in,
                              void* d_out, int out_size) {
    (void)in_sizes; (void)n_in; (void)out_size;
    const float* x   = (const float*)d_in[0];
    const float* adj = (const float*)d_in[1];
    const float* W1  = (const float*)d_in[2];
    const float* b1  = (const float*)d_in[3];
    const float* W2  = (const float*)d_in[4];
    const float* b2  = (const float*)d_in[5];
    const float* W3  = (const float*)d_in[6];
    const float* b3  = (const float*)d_in[7];
    const float* W4  = (const float*)d_in[8];
    const float* b4  = (const float*)d_in[9];

    __half* adjh = (__half*)symaddr(g_adj);
    bf16* x_hi   = (bf16*)symaddr(g_x_hi);
    bf16* x_lo   = (bf16*)symaddr(g_x_lo);
    bf16* hA_hi  = (bf16*)symaddr(g_hA_hi);
    bf16* hA_lo  = (bf16*)symaddr(g_hA_lo);
    bf16* hB_hi  = (bf16*)symaddr(g_hB_hi);
    bf16* hB_lo  = (bf16*)symaddr(g_hB_lo);
    __half* yt   = (__half*)symaddr(g_yt);
    bf16* wt_hi  = (bf16*)symaddr(g_wt_hi);
    bf16* wt_lo  = (bf16*)symaddr(g_wt_lo);
    float* z     = (float*)symaddr(g_z);
    float* part  = (float*)symaddr(g_part);

    cudaFuncSetAttribute(k_gemm, cudaFuncAttributeMaxDynamicSharedMemorySize, 98304);
    cudaFuncSetAttribute(k_agg, cudaFuncAttributeMaxDynamicSharedMemorySize, 49152);

    const dim3 gAgg(1, 128, NZ_AGG), gLin(1, 128, 1);

    // prep
    k_xcat<<<2048, 256>>>((const float4*)x, x_hi, x_lo);
    k_tsplit<<<dim3(4, 16), dim3(32, 8)>>>(W1, 512, 128, wt_hi, wt_lo);
    // y1 = x @ W1_bot -> yt fp16
    k_gemm<<<gLin, 128, 98304>>>(x_hi, x_lo, 256, wt_hi + 256, wt_lo + 256, 512,
        256, 6, 128, nullptr, nullptr, nullptr, nullptr, 0, yt, nullptr);
    // adj fp16 (profiled launch #4)
    k_split<<<4096, 256>>>((const float4*)adj, (uint4*)adjh, (size_t)NN * NN / 8);
    // z1 = adj @ y1
    k_agg<<<gAgg, 128, 49152>>>(adjh, NN, yt, NN, NN, part);
    k_reducef<<<1024, 256>>>((const float4*)part, NZ_AGG, (float4*)z);
    k_tsplit<<<dim3(4, 8), dim3(32, 8)>>>(W2, 256, 128, wt_hi + 65536,  wt_lo + 65536);
    k_tsplit<<<dim3(4, 8), dim3(32, 8)>>>(W3, 256, 128, wt_hi + 98304,  wt_lo + 98304);
    k_tsplit<<<dim3(2, 8), dim3(32, 8)>>>(W4, 256, 64,  wt_hi + 131072, wt_lo + 131072);
    // h2 = relu(x @ W1_top + z + b1) -> hA
    k_gemm<<<gLin, 128, 98304>>>(x_hi, x_lo, 256, wt_hi, wt_lo, 512,
        256, 4, 128, b1, z, hA_hi, hA_lo, 128, nullptr, nullptr);

    // ---- layer 2 ----
    k_gemm<<<gLin, 128, 98304>>>(hA_hi, hA_lo, 128,
        wt_hi + 65536 + 128, wt_lo + 65536 + 128, 256,
        128, 6, 128, nullptr, nullptr, nullptr, nullptr, 0, yt, nullptr);
    k_agg<<<gAgg, 128, 49152>>>(adjh, NN, yt, NN, NN, part);
    k_reducef<<<1024, 256>>>((const float4*)part, NZ_AGG, (float4*)z);
    k_gemm<<<gLin, 128, 98304>>>(hA_hi, hA_lo, 128,
        wt_hi + 65536, wt_lo + 65536, 256,
        128, 4, 128, b2, z, hB_hi, hB_lo, 128, nullptr, nullptr);

    // ---- layer 3 ----
    k_gemm<<<gLin, 128, 98304>>>(hB_hi, hB_lo, 128,
        wt_hi + 98304 + 128, wt_lo + 98304 + 128, 256,
        128, 6, 128, nullptr, nullptr, nullptr, nullptr, 0, yt, nullptr);
    k_agg<<<gAgg, 128, 49152>>>(adjh, NN, yt, NN, NN, part);
    k_reducef<<<1024, 256>>>((const float4*)part, NZ_AGG, (float4*)z);
    k_gemm<<<gLin, 128, 98304>>>(hB_hi, hB_lo, 128,
        wt_hi + 98304, wt_lo + 98304, 256,
        128, 4, 128, b3, z, hA_hi, hA_lo, 128, nullptr, nullptr);

    // ---- layer 4 (N=64; W4^T rows 64..127 zero -> y/z cols 64..127 zero) ----
    k_gemm<<<gLin, 128, 98304>>>(hA_hi, hA_lo, 128,
        wt_hi + 131072 + 128, wt_lo + 131072 + 128, 256,
        128, 6, 128, nullptr, nullptr, nullptr, nullptr, 0, yt, nullptr);
    k_agg<<<gAgg, 128, 49152>>>(adjh, NN, yt, NN, NN, part);
    k_reducef<<<1024, 256>>>((const float4*)part, NZ_AGG, (float4*)z);
    k_gemm<<<gLin, 128, 98304>>>(hA_hi, hA_lo, 128,
        wt_hi + 131072, wt_lo + 131072, 256,
        128, 5, 64, b4, z, nullptr, nullptr, 0, nullptr, (float*)d_out);
}

// round 14
// speedup vs baseline: 2.2361x; 1.0241x over previous
#include <cuda_runtime.h>
#include <cuda_bf16.h>
#include <cuda_fp16.h>
#include <cstdint>
#include <cstddef>

typedef __nv_bfloat16 bf16;

#define NN 8192
#define ADJ_SCALE 4096.0f
#define ADJ_ISCALE (1.0f / 4096.0f)
#define NZ_AGG 10

// ---------------- device scratch (no allocs; zero-init at load) ----------------
__device__ __align__(1024) __half g_adj[(size_t)NN * NN];     // adj*4096 fp16
__device__ __align__(1024) bf16 g_x_hi[NN * 256];             // x split, ld 256
__device__ __align__(1024) bf16 g_x_lo[NN * 256];
__device__ __align__(1024) bf16 g_hA_hi[NN * 128];            // layer outputs ping-pong
__device__ __align__(1024) bf16 g_hA_lo[NN * 128];
__device__ __align__(1024) bf16 g_hB_hi[NN * 128];
__device__ __align__(1024) bf16 g_hB_lo[NN * 128];
__device__ __align__(1024) __half g_yt[128 * NN];             // y^T fp16 [128][NN]
__device__ __align__(1024) bf16 g_wt_hi[163840];              // W^T; L4 zero-padded
__device__ __align__(1024) bf16 g_wt_lo[163840];
__device__ __align__(1024) __half g_part[(size_t)NZ_AGG * NN * 128];  // fp16 partials

// ---------------- helpers ----------------
__device__ __forceinline__ uint32_t s2u(const void* p) {
    uint32_t a;
    asm("{ .reg .u64 t; cvta.to.shared.u64 t, %1; cvt.u32.u64 %0, t; }" : "=r"(a) : "l"(p));
    return a;
}

#define CP16(dst_u32, src_ptr) \
    asm volatile("cp.async.cg.shared.global [%0], [%1], 16;" :: "r"(dst_u32), "l"(src_ptr) : "memory")

__device__ __forceinline__ void ldsm4(uint32_t a[4], uint32_t addr) {
    asm volatile("ldmatrix.sync.aligned.m8n8.x4.shared.b16 {%0,%1,%2,%3}, [%4];"
                 : "=r"(a[0]), "=r"(a[1]), "=r"(a[2]), "=r"(a[3]) : "r"(addr));
}

__device__ __forceinline__ void mma_bf16(float c[4], const uint32_t a[4], const uint32_t b[2]) {
    asm volatile(
        "mma.sync.aligned.m16n8k16.row.col.f32.bf16.bf16.f32 "
        "{%0,%1,%2,%3}, {%4,%5,%6,%7}, {%8,%9}, {%0,%1,%2,%3};"
        : "+f"(c[0]), "+f"(c[1]), "+f"(c[2]), "+f"(c[3])
        : "r"(a[0]), "r"(a[1]), "r"(a[2]), "r"(a[3]), "r"(b[0]), "r"(b[1]));
}

__device__ __forceinline__ void mma_f16(float c[4], const uint32_t a[4], const uint32_t b[2]) {
    asm volatile(
        "mma.sync.aligned.m16n8k16.row.col.f32.f16.f16.f32 "
        "{%0,%1,%2,%3}, {%4,%5,%6,%7}, {%8,%9}, {%0,%1,%2,%3};"
        : "+f"(c[0]), "+f"(c[1]), "+f"(c[2]), "+f"(c[3])
        : "r"(a[0]), "r"(a[1]), "r"(a[2]), "r"(a[3]), "r"(b[0]), "r"(b[1]));
}

__device__ __forceinline__ void split2(float v, bf16& h, bf16& l) {
    h = __float2bfloat16(v);
    l = __float2bfloat16(v - __bfloat162float(h));
}

// ---------------- prep kernels ----------------
// adj fp32 -> (adj*4096) single fp16; streaming
__global__ void k_split(const float4* __restrict__ src, uint4* __restrict__ dst,
                        size_t n8) {
    size_t i = (size_t)blockIdx.x * blockDim.x + threadIdx.x;
    size_t stride = (size_t)gridDim.x * blockDim.x;
    for (; i < n8; i += stride) {
        float4 a = __ldcs(src + 2 * i);
        float4 b = __ldcs(src + 2 * i + 1);
        uint4 H;
        __half2* Hp = (__half2*)&H;
        Hp[0] = __floats2half2_rn(a.x * ADJ_SCALE, a.y * ADJ_SCALE);
        Hp[1] = __floats2half2_rn(a.z * ADJ_SCALE, a.w * ADJ_SCALE);
        Hp[2] = __floats2half2_rn(b.x * ADJ_SCALE, b.y * ADJ_SCALE);
        Hp[3] = __floats2half2_rn(b.z * ADJ_SCALE, b.w * ADJ_SCALE);
        __stcs(dst + i, H);
    }
}

// x [8192,256] fp32 -> split row-major ld 256
__global__ void k_xcat(const float4* __restrict__ x4, bf16* __restrict__ hi,
                       bf16* __restrict__ lo) {
    int idx = blockIdx.x * blockDim.x + threadIdx.x;  // 8192*64
    float4 v = x4[idx];
    size_t base = (size_t)idx * 4;
    bf16 h0, h1, h2, h3, l0, l1, l2, l3;
    split2(v.x, h0, l0); split2(v.y, h1, l1);
    split2(v.z, h2, l2); split2(v.w, h3, l3);
    __nv_bfloat162* H = (__nv_bfloat162*)(hi + base);
    __nv_bfloat162* L = (__nv_bfloat162*)(lo + base);
    H[0] = __halves2bfloat162(h0, h1); H[1] = __halves2bfloat162(h2, h3);
    L[0] = __halves2bfloat162(l0, l1); L[1] = __halves2bfloat162(l2, l3);
}

// transpose + split: src [R, C] fp32 -> dst[c][r] split bf16 (dst ld = R)
__global__ void k_tsplit(const float* __restrict__ src, int R, int C,
                         bf16* __restrict__ dhi, bf16* __restrict__ dlo) {
    __shared__ float t[32][33];
    int bx = blockIdx.x * 32;
    int by = blockIdx.y * 32;
    int tx = threadIdx.x, ty = threadIdx.y;
    #pragma unroll
    for (int i = 0; i < 4; i++)
        t[ty + 8 * i][tx] = src[(size_t)(by + ty + 8 * i) * C + bx + tx];
    __syncthreads();
    #pragma unroll
    for (int i = 0; i < 4; i++) {
        int c = bx + ty + 8 * i;
        float v = t[tx][ty + 8 * i];
        bf16 h, l; split2(v, h, l);
        dhi[(size_t)c * R + by + tx] = h;
        dlo[(size_t)c * R + by + tx] = l;
    }
}

// ---------------- fp16 single-product aggregation GEMM ----------------
// partials[z] = A(fp16)[64, K] @ B(fp16)[128, K]^T  (fp16 out, scaled by 4096)
// 128 threads, 4 warps (2m x 2n), BM=64, BN=128. Stage 24KB (A@0 8K, B@8K 16K),
// 3 stages, 3 CTAs/SM. Split-K via blockIdx.z (uneven chunk ranges).
#define AGG_STAGE 24576u
#define AGG_SMEM (3 * 24576)

__device__ __forceinline__ void agg_load_stage(
    uint32_t sb, int stage, int kc,
    const __half* A, int lda, const __half* B, int ldb,
    int m0, int n0, int tid) {
    uint32_t st = sb + (uint32_t)stage * AGG_STAGE;
    #pragma unroll
    for (int i = 0; i < 4; ++i) {           // A: 512 x 16B
        int g = tid + (i << 7);
        int row = g >> 3;
        int cb = (g & 7) << 4;
        uint32_t dst = st + (uint32_t)(row * 128) + (uint32_t)(cb ^ ((row & 7) << 4));
        CP16(dst, (const char*)(A + (size_t)(m0 + row) * lda + kc) + cb);
    }
    #pragma unroll
    for (int i = 0; i < 8; ++i) {           // B: 1024 x 16B
        int g = tid + (i << 7);
        int row = g >> 3;
        int cb = (g & 7) << 4;
        uint32_t dst = st + 8192u + (uint32_t)(row * 128) + (uint32_t)(cb ^ ((row & 7) << 4));
        CP16(dst, (const char*)(B + (size_t)(n0 + row) * ldb + kc) + cb);
    }
}

struct AggFrags { uint32_t ah[2][4], bh[4][4]; };

__device__ __forceinline__ void agg_frag_load(uint32_t aB, uint32_t bB, int kq,
                                              uint32_t acol, uint32_t axr,
                                              uint32_t bcol, uint32_t bxr, AggFrags& f) {
    uint32_t ac = ((uint32_t)(kq * 32) + acol) ^ axr;
    uint32_t bc = ((uint32_t)(kq * 32) + bcol) ^ bxr;
    #pragma unroll
    for (int mi = 0; mi < 2; ++mi)
        ldsm4(f.ah[mi], aB + (uint32_t)(mi * 2048) + ac);
    #pragma unroll
    for (int j = 0; j < 4; ++j)
        ldsm4(f.bh[j], bB + (uint32_t)(j * 2048) + bc);
}

__device__ __forceinline__ void agg_frag_mma(float acc[2][8][4], const AggFrags& f) {
    #pragma unroll
    for (int mi = 0; mi < 2; ++mi)
        #pragma unroll
        for (int ni = 0; ni < 8; ++ni)
            mma_f16(acc[mi][ni], f.ah[mi], &f.bh[ni >> 1][(ni & 1) * 2]);
}

__global__ void __launch_bounds__(128, 3)
k_agg(const __half* __restrict__ A, int lda, const __half* __restrict__ B, int ldb,
      int K, __half* __restrict__ of) {
    extern __shared__ char smem[];
    const int tid = threadIdx.x;
    const uint32_t sb = s2u(smem);
    const int m0 = (int)blockIdx.y * 64;
    const int n0 = (int)blockIdx.x * 128;
    const int CT = K >> 6;
    const int nz = (int)gridDim.z;
    const int c0 = (int)((size_t)blockIdx.z * CT / nz);
    const int c1 = (int)(((size_t)blockIdx.z + 1) * CT / nz);
    const int lane = tid & 31, wid = tid >> 5;
    const int wm = wid >> 1, wn = wid & 1;
    const int lg = lane >> 3, lr = lane & 7;

    const int arow = wm * 32 + (lg & 1) * 8 + lr;
    const uint32_t acol = (uint32_t)((lg >> 1) * 16);
    const uint32_t axr = (uint32_t)((arow & 7) << 4);
    const int brow = wn * 64 + (lg >> 1) * 8 + lr;
    const uint32_t bcol = (uint32_t)((lg & 1) * 16);
    const uint32_t bxr = (uint32_t)((brow & 7) << 4);

    float acc[2][8][4] = {};

    // prologue: 3 stages (chunks-per-CTA >= 12 always)
    #pragma unroll
    for (int p = 0; p < 3; ++p) {
        agg_load_stage(sb, p, (c0 + p) << 6, A, lda, B, ldb, m0, n0, tid);
        asm volatile("cp.async.commit_group;" ::: "memory");
    }

    for (int c = c0; c < c1; ++c) {
        asm volatile("cp.async.wait_group 2;" ::: "memory");
        __syncthreads();

        int sidx = (c - c0) % 3;
        uint32_t st = sb + (uint32_t)(sidx * AGG_STAGE);
        uint32_t aB = st + (uint32_t)(arow * 128);
        uint32_t bB = st + 8192u + (uint32_t)(brow * 128);

        AggFrags f;
        #pragma unroll
        for (int kq = 0; kq < 3; ++kq) {
            agg_frag_load(aB, bB, kq, acol, axr, bcol, bxr, f);
            agg_frag_mma(acc, f);
        }
        agg_frag_load(aB, bB, 3, acol, axr, bcol, bxr, f);
        __syncthreads();
        int nc = c + 3;
        if (nc < c1)
            agg_load_stage(sb, sidx, nc << 6, A, lda, B, ldb, m0, n0, tid);
        asm volatile("cp.async.commit_group;" ::: "memory");
        agg_frag_mma(acc, f);
    }

    // epilogue: fp16 partials (still scaled by ADJ_SCALE)
    of += (size_t)blockIdx.z * NN * 128;
    #pragma unroll
    for (int mi = 0; mi < 2; ++mi) {
        int r0 = m0 + wm * 32 + mi * 16 + (lane >> 2);
        #pragma unroll
        for (int ni = 0; ni < 8; ++ni) {
            int c = n0 + wn * 64 + ni * 8 + ((lane & 3) << 1);
            *(__half2*)(of + (size_t)r0 * 128 + c) =
                __floats2half2_rn(acc[mi][ni][0], acc[mi][ni][1]);
            *(__half2*)(of + (size_t)(r0 + 8) * 128 + c) =
                __floats2half2_rn(acc[mi][ni][2], acc[mi][ni][3]);
        }
    }
}

// ---------------- bf16 3-product GEMM (linears) ----------------
// 128 threads, BM=64, BN=128, stage 48KB, 2 stages, 2 CTAs/SM.
// mode 4: relu(v + sum(partials)*ISCALE + bias) -> split bf16 orm (ld_rm)
// mode 5: v + sum(partials)*ISCALE + bias -> fp32 of (ld Ncols), guard c < Ncols
// mode 6: v -> transposed fp16 yt (ld NN)
#define LIN_STAGE 49152u

__device__ __forceinline__ void lin_load_stage(
    uint32_t sb, int stage, int kc,
    const bf16* Ah, const bf16* Al, int lda,
    const bf16* Bh, const bf16* Bl, int ldb,
    int m0, int n0, int tid) {
    uint32_t st = sb + (uint32_t)stage * LIN_STAGE;
    #pragma unroll
    for (int i = 0; i < 8; ++i) {
        int g = tid + (i << 7);
        int sub = g >> 9;
        int idx = g & 511;
        int row = idx >> 3;
        int cb = (idx & 7) << 4;
        uint32_t dst = st + (uint32_t)(sub * 8192) + (uint32_t)(row * 128)
                     + (uint32_t)(cb ^ ((row & 7) << 4));
        const bf16* srcb = sub ? Al : Ah;
        CP16(dst, (const char*)(srcb + (size_t)(m0 + row) * lda + kc) + cb);
    }
    #pragma unroll
    for (int i = 0; i < 16; ++i) {
        int g = tid + (i << 7);
        int sub = g >> 10;
        int idx = g & 1023;
        int row = idx >> 3;
        int cb = (idx & 7) << 4;
        uint32_t dst = st + 16384u + (uint32_t)(sub * 16384) + (uint32_t)(row * 128)
                     + (uint32_t)(cb ^ ((row & 7) << 4));
        const bf16* srcb = sub ? Bl : Bh;
        CP16(dst, (const char*)(srcb + (size_t)(n0 + row) * ldb + kc) + cb);
    }
}

struct Frags { uint32_t ah[2][4], al[2][4], bh[4][4], bl[4][4]; };

__device__ __forceinline__ void lin_frag_load(uint32_t aB, uint32_t bB, int kq,
                                              uint32_t acol, uint32_t axr,
                                              uint32_t bcol, uint32_t bxr, Frags& f) {
    uint32_t ac = ((uint32_t)(kq * 32) + acol) ^ axr;
    uint32_t bc = ((uint32_t)(kq * 32) + bcol) ^ bxr;
    #pragma unroll
    for (int mi = 0; mi < 2; ++mi) {
        ldsm4(f.ah[mi], aB + (uint32_t)(mi * 2048) + ac);
        ldsm4(f.al[mi], aB + 8192u + (uint32_t)(mi * 2048) + ac);
    }
    #pragma unroll
    for (int j = 0; j < 4; ++j) {
        ldsm4(f.bh[j], bB + (uint32_t)(j * 2048) + bc);
        ldsm4(f.bl[j], bB + 16384u + (uint32_t)(j * 2048) + bc);
    }
}

__device__ __forceinline__ void lin_frag_mma(float acc[2][8][4], const Frags& f) {
    #pragma unroll
    for (int mi = 0; mi < 2; ++mi)
        #pragma unroll
        for (int ni = 0; ni < 8; ++ni)
            mma_bf16(acc[mi][ni], f.ah[mi], &f.bh[ni >> 1][(ni & 1) * 2]);
    #pragma unroll
    for (int mi = 0; mi < 2; ++mi)
        #pragma unroll
        for (int ni = 0; ni < 8; ++ni)
            mma_bf16(acc[mi][ni], f.ah[mi], &f.bl[ni >> 1][(ni & 1) * 2]);
    #pragma unroll
    for (int mi = 0; mi < 2; ++mi)
        #pragma unroll
        for (int ni = 0; ni < 8; ++ni)
            mma_bf16(acc[mi][ni], f.al[mi], &f.bh[ni >> 1][(ni & 1) * 2]);
}

__global__ void __launch_bounds__(128, 2)
k_gemm(const bf16* __restrict__ Ah, const bf16* __restrict__ Al, int lda,
       const bf16* __restrict__ Bh, const bf16* __restrict__ Bl, int ldb,
       int K, int mode, int Ncols, const float* __restrict__ bias,
       const __half* __restrict__ zin,
       bf16* __restrict__ orm_hi, bf16* __restrict__ orm_lo, int ld_rm,
       __half* __restrict__ yt,
       float* __restrict__ of) {
    extern __shared__ char smem[];
    const int tid = threadIdx.x;
    const uint32_t sb = s2u(smem);
    const int m0 = (int)blockIdx.y * 64;
    const int n0 = (int)blockIdx.x * 128;
    const int C = K >> 6;
    const int lane = tid & 31, wid = tid >> 5;
    const int wm = wid >> 1, wn = wid & 1;
    const int lg = lane >> 3, lr = lane & 7;

    const int arow = wm * 32 + (lg & 1) * 8 + lr;
    const uint32_t acol = (uint32_t)((lg >> 1) * 16);
    const uint32_t axr = (uint32_t)((arow & 7) << 4);
    const int brow = wn * 64 + (lg >> 1) * 8 + lr;
    const uint32_t bcol = (uint32_t)((lg & 1) * 16);
    const uint32_t bxr = (uint32_t)((brow & 7) << 4);

    float acc[2][8][4] = {};

    lin_load_stage(sb, 0, 0, Ah, Al, lda, Bh, Bl, ldb, m0, n0, tid);
    asm volatile("cp.async.commit_group;" ::: "memory");
    lin_load_stage(sb, 1, 64, Ah, Al, lda, Bh, Bl, ldb, m0, n0, tid);
    asm volatile("cp.async.commit_group;" ::: "memory");

    for (int c = 0; c < C; ++c) {
        asm volatile("cp.async.wait_group 1;" ::: "memory");
        __syncthreads();

        uint32_t st = sb + (uint32_t)((c & 1) * LIN_STAGE);
        uint32_t aB = st + (uint32_t)(arow * 128);
        uint32_t bB = st + 16384u + (uint32_t)(brow * 128);

        Frags f;
        #pragma unroll
        for (int kq = 0; kq < 3; ++kq) {
            lin_frag_load(aB, bB, kq, acol, axr, bcol, bxr, f);
            lin_frag_mma(acc, f);
        }
        lin_frag_load(aB, bB, 3, acol, axr, bcol, bxr, f);
        __syncthreads();
        int nc = c + 2;
        if (nc < C)
            lin_load_stage(sb, c & 1, nc << 6, Ah, Al, lda, Bh, Bl, ldb, m0, n0, tid);
        asm volatile("cp.async.commit_group;" ::: "memory");
        lin_frag_mma(acc, f);
    }

    #pragma unroll
    for (int mi = 0; mi < 2; ++mi) {
        int r0 = m0 + wm * 32 + mi * 16 + (lane >> 2);
        #pragma unroll
        for (int ni = 0; ni < 8; ++ni) {
            int c = n0 + wn * 64 + ni * 8 + ((lane & 3) << 1);
            float v0 = acc[mi][ni][0], v1 = acc[mi][ni][1];
            float v2 = acc[mi][ni][2], v3 = acc[mi][ni][3];
            if (mode == 6) {
                yt[(size_t)c * NN + r0]           = __float2half_rn(v0);
                yt[(size_t)(c + 1) * NN + r0]     = __float2half_rn(v1);
                yt[(size_t)c * NN + r0 + 8]       = __float2half_rn(v2);
                yt[(size_t)(c + 1) * NN + r0 + 8] = __float2half_rn(v3);
            } else {
                // fused reduction of NZ_AGG fp16 partials (L2-hot)
                float z0 = 0.f, z1 = 0.f, z2 = 0.f, z3 = 0.f;
                #pragma unroll
                for (int q = 0; q < NZ_AGG; ++q) {
                    const __half* pq = zin + (size_t)q * NN * 128;
                    float2 fa = __half22float2(*(const __half2*)(pq + (size_t)r0 * 128 + c));
                    float2 fb = __half22float2(*(const __half2*)(pq + (size_t)(r0 + 8) * 128 + c));
                    z0 += fa.x; z1 += fa.y; z2 += fb.x; z3 += fb.y;
                }
                float b0v = bias[c], b1v = bias[c + 1];
                v0 += z0 * ADJ_ISCALE + b0v; v1 += z1 * ADJ_ISCALE + b1v;
                v2 += z2 * ADJ_ISCALE + b0v; v3 += z3 * ADJ_ISCALE + b1v;
                if (mode == 5) {
                    if (c < Ncols) {
                        *(float2*)(of + (size_t)r0 * Ncols + c)       = make_float2(v0, v1);
                        *(float2*)(of + (size_t)(r0 + 8) * Ncols + c) = make_float2(v2, v3);
                    }
                } else {  // mode 4
                    v0 = fmaxf(v0, 0.f); v1 = fmaxf(v1, 0.f);
                    v2 = fmaxf(v2, 0.f); v3 = fmaxf(v3, 0.f);
                    bf16 h0, l0, h1, l1, h2, l2, h3, l3;
                    split2(v0, h0, l0); split2(v1, h1, l1);
                    split2(v2, h2, l2); split2(v3, h3, l3);
                    *(__nv_bfloat162*)(orm_hi + (size_t)r0 * ld_rm + c) = __halves2bfloat162(h0, h1);
                    *(__nv_bfloat162*)(orm_lo + (size_t)r0 * ld_rm + c) = __halves2bfloat162(l0, l1);
                    *(__nv_bfloat162*)(orm_hi + (size_t)(r0 + 8) * ld_rm + c) = __halves2bfloat162(h2, h3);
                    *(__nv_bfloat162*)(orm_lo + (size_t)(r0 + 8) * ld_rm + c) = __halves2bfloat162(l2, l3);
                }
            }
        }
    }
}

// ---------------- host ----------------
static void* symaddr(const void* sym) {
    void* p = nullptr;
    cudaGetSymbolAddress(&p, sym);
    return p;
}

extern "C" void kernel_launch(void* const* d_in, const int* in_sizes, int n_in,
                              void* d_out, int out_size) {
    (void)in_sizes; (void)n_in; (void)out_size;
    const float* x   = (const float*)d_in[0];
    const float* adj = (const float*)d_in[1];
    const float* W1  = (const float*)d_in[2];
    const float* b1  = (const float*)d_in[3];
    const float* W2  = (const float*)d_in[4];
    const float* b2  = (const float*)d_in[5];
    const float* W3  = (const float*)d_in[6];
    const float* b3  = (const float*)d_in[7];
    const float* W4  = (const float*)d_in[8];
    const float* b4  = (const float*)d_in[9];

    __half* adjh = (__half*)symaddr(g_adj);
    bf16* x_hi   = (bf16*)symaddr(g_x_hi);
    bf16* x_lo   = (bf16*)symaddr(g_x_lo);
    bf16* hA_hi  = (bf16*)symaddr(g_hA_hi);
    bf16* hA_lo  = (bf16*)symaddr(g_hA_lo);
    bf16* hB_hi  = (bf16*)symaddr(g_hB_hi);
    bf16* hB_lo  = (bf16*)symaddr(g_hB_lo);
    __half* yt   = (__half*)symaddr(g_yt);
    bf16* wt_hi  = (bf16*)symaddr(g_wt_hi);
    bf16* wt_lo  = (bf16*)symaddr(g_wt_lo);
    __half* part = (__half*)symaddr(g_part);

    cudaFuncSetAttribute(k_gemm, cudaFuncAttributeMaxDynamicSharedMemorySize, 98304);
    cudaFuncSetAttribute(k_agg, cudaFuncAttributeMaxDynamicSharedMemorySize, AGG_SMEM);

    const dim3 gAgg(1, 128, NZ_AGG), gLin(1, 128, 1);

    // 1: adj fp16 (DRAM-bound, at roofline)
    k_split<<<4096, 256>>>((const float4*)adj, (uint4*)adjh, (size_t)NN * NN / 8);
    // 2: x split
    k_xcat<<<2048, 256>>>((const float4*)x, x_hi, x_lo);
    // 3: W1^T
    k_tsplit<<<dim3(4, 16), dim3(32, 8)>>>(W1, 512, 128, wt_hi, wt_lo);
    // 4: y1 = x @ W1_bot -> yt fp16  [PROFILED]
    k_gemm<<<gLin, 128, 98304>>>(x_hi, x_lo, 256, wt_hi + 256, wt_lo + 256, 512,
        256, 6, 128, nullptr, nullptr, nullptr, nullptr, 0, yt, nullptr);
    // 5: z1 partials = adj @ y1
    k_agg<<<gAgg, 128, AGG_SMEM>>>(adjh, NN, yt, NN, NN, part);
    // 6-8: remaining weight transposes (overlap agg tail)
    k_tsplit<<<dim3(4, 8), dim3(32, 8)>>>(W2, 256, 128, wt_hi + 65536,  wt_lo + 65536);
    k_tsplit<<<dim3(4, 8), dim3(32, 8)>>>(W3, 256, 128, wt_hi + 98304,  wt_lo + 98304);
    k_tsplit<<<dim3(2, 8), dim3(32, 8)>>>(W4, 256, 64,  wt_hi + 131072, wt_lo + 131072);
    // 9: h2 = relu(x @ W1_top + z + b1) -> hA   (fused partial reduction)
    k_gemm<<<gLin, 128, 98304>>>(x_hi, x_lo, 256, wt_hi, wt_lo, 512,
        256, 4, 128, b1, part, hA_hi, hA_lo, 128, nullptr, nullptr);

    // ---- layer 2 ----
    k_gemm<<<gLin, 128, 98304>>>(hA_hi, hA_lo, 128,
        wt_hi + 65536 + 128, wt_lo + 65536 + 128, 256,
        128, 6, 128, nullptr, nullptr, nullptr, nullptr, 0, yt, nullptr);
    k_agg<<<gAgg, 128, AGG_SMEM>>>(adjh, NN, yt, NN, NN, part);
    k_gemm<<<gLin, 128, 98304>>>(hA_hi, hA_lo, 128,
        wt_hi + 65536, wt_lo + 65536, 256,
        128, 4, 128, b2, part, hB_hi, hB_lo, 128, nullptr, nullptr);

    // ---- layer 3 ----
    k_gemm<<<gLin, 128, 98304>>>(hB_hi, hB_lo, 128,
        wt_hi + 98304 + 128, wt_lo + 98304 + 128, 256,
        128, 6, 128, nullptr, nullptr, nullptr, nullptr, 0, yt, nullptr);
    k_agg<<<gAgg, 128, AGG_SMEM>>>(adjh, NN, yt, NN, NN, part);
    k_gemm<<<gLin, 128, 98304>>>(hB_hi, hB_lo, 128,
        wt_hi + 98304, wt_lo + 98304, 256,
        128, 4, 128, b3, part, hA_hi, hA_lo, 128, nullptr, nullptr);

    // ---- layer 4 (N=64; W4^T rows 64..127 zero -> y/z cols 64..127 zero) ----
    k_gemm<<<gLin, 128, 98304>>>(hA_hi, hA_lo, 128,
        wt_hi + 131072 + 128, wt_lo + 131072 + 128, 256,
        128, 6, 128, nullptr, nullptr, nullptr, nullptr, 0, yt, nullptr);
    k_agg<<<gAgg, 128, AGG_SMEM>>>(adjh, NN, yt, NN, NN, part);
    k_gemm<<<gLin, 128, 98304>>>(hA_hi, hA_lo, 128,
        wt_hi + 131072, wt_lo + 131072, 256,
        128, 5, 64, b4, part, nullptr, nullptr, 0, nullptr, (float*)d_out);
}

// round 15
// speedup vs baseline: 2.2780x; 1.0187x over previous
#include <cuda_runtime.h>
#include <cuda_bf16.h>
#include <cuda_fp16.h>
#include <cstdint>
#include <cstddef>

typedef __nv_bfloat16 bf16;

#define NN 8192
#define ADJ_SCALE 4096.0f
#define ADJ_ISCALE (1.0f / 4096.0f)
#define NZ_AGG 10

// ---------------- device scratch (no allocs; zero-init at load) ----------------
__device__ __align__(1024) __half g_adj[(size_t)NN * NN];     // adj*4096 fp16
__device__ __align__(1024) bf16 g_x_hi[NN * 256];             // x split, ld 256
__device__ __align__(1024) bf16 g_x_lo[NN * 256];
__device__ __align__(1024) bf16 g_hA_hi[NN * 128];            // layer outputs ping-pong
__device__ __align__(1024) bf16 g_hA_lo[NN * 128];
__device__ __align__(1024) bf16 g_hB_hi[NN * 128];
__device__ __align__(1024) bf16 g_hB_lo[NN * 128];
__device__ __align__(1024) __half g_yt[128 * NN];             // y^T fp16 [128][NN]
__device__ __align__(1024) bf16 g_wt_hi[163840];              // W^T; L4 zero-padded
__device__ __align__(1024) bf16 g_wt_lo[163840];
__device__ __align__(1024) __half g_part[(size_t)NZ_AGG * NN * 128];  // fp16 partials

// ---------------- helpers ----------------
__device__ __forceinline__ uint32_t s2u(const void* p) {
    uint32_t a;
    asm("{ .reg .u64 t; cvta.to.shared.u64 t, %1; cvt.u32.u64 %0, t; }" : "=r"(a) : "l"(p));
    return a;
}

#define CP16(dst_u32, src_ptr) \
    asm volatile("cp.async.cg.shared.global [%0], [%1], 16;" :: "r"(dst_u32), "l"(src_ptr) : "memory")

__device__ __forceinline__ void ldsm4(uint32_t a[4], uint32_t addr) {
    asm volatile("ldmatrix.sync.aligned.m8n8.x4.shared.b16 {%0,%1,%2,%3}, [%4];"
                 : "=r"(a[0]), "=r"(a[1]), "=r"(a[2]), "=r"(a[3]) : "r"(addr));
}

__device__ __forceinline__ void mma_bf16(float c[4], const uint32_t a[4], const uint32_t b[2]) {
    asm volatile(
        "mma.sync.aligned.m16n8k16.row.col.f32.bf16.bf16.f32 "
        "{%0,%1,%2,%3}, {%4,%5,%6,%7}, {%8,%9}, {%0,%1,%2,%3};"
        : "+f"(c[0]), "+f"(c[1]), "+f"(c[2]), "+f"(c[3])
        : "r"(a[0]), "r"(a[1]), "r"(a[2]), "r"(a[3]), "r"(b[0]), "r"(b[1]));
}

__device__ __forceinline__ void mma_f16(float c[4], const uint32_t a[4], const uint32_t b[2]) {
    asm volatile(
        "mma.sync.aligned.m16n8k16.row.col.f32.f16.f16.f32 "
        "{%0,%1,%2,%3}, {%4,%5,%6,%7}, {%8,%9}, {%0,%1,%2,%3};"
        : "+f"(c[0]), "+f"(c[1]), "+f"(c[2]), "+f"(c[3])
        : "r"(a[0]), "r"(a[1]), "r"(a[2]), "r"(a[3]), "r"(b[0]), "r"(b[1]));
}

__device__ __forceinline__ void split2(float v, bf16& h, bf16& l) {
    h = __float2bfloat16(v);
    l = __float2bfloat16(v - __bfloat162float(h));
}

// ---------------- prep kernels ----------------
// adj fp32 -> (adj*4096) single fp16; streaming
__global__ void k_split(const float4* __restrict__ src, uint4* __restrict__ dst,
                        size_t n8) {
    size_t i = (size_t)blockIdx.x * blockDim.x + threadIdx.x;
    size_t stride = (size_t)gridDim.x * blockDim.x;
    for (; i < n8; i += stride) {
        float4 a = __ldcs(src + 2 * i);
        float4 b = __ldcs(src + 2 * i + 1);
        uint4 H;
        __half2* Hp = (__half2*)&H;
        Hp[0] = __floats2half2_rn(a.x * ADJ_SCALE, a.y * ADJ_SCALE);
        Hp[1] = __floats2half2_rn(a.z * ADJ_SCALE, a.w * ADJ_SCALE);
        Hp[2] = __floats2half2_rn(b.x * ADJ_SCALE, b.y * ADJ_SCALE);
        Hp[3] = __floats2half2_rn(b.z * ADJ_SCALE, b.w * ADJ_SCALE);
        __stcs(dst + i, H);
    }
}

// x [8192,256] fp32 -> split row-major ld 256
__global__ void k_xcat(const float4* __restrict__ x4, bf16* __restrict__ hi,
                       bf16* __restrict__ lo) {
    int idx = blockIdx.x * blockDim.x + threadIdx.x;  // 8192*64
    float4 v = x4[idx];
    size_t base = (size_t)idx * 4;
    bf16 h0, h1, h2, h3, l0, l1, l2, l3;
    split2(v.x, h0, l0); split2(v.y, h1, l1);
    split2(v.z, h2, l2); split2(v.w, h3, l3);
    __nv_bfloat162* H = (__nv_bfloat162*)(hi + base);
    __nv_bfloat162* L = (__nv_bfloat162*)(lo + base);
    H[0] = __halves2bfloat162(h0, h1); H[1] = __halves2bfloat162(h2, h3);
    L[0] = __halves2bfloat162(l0, l1); L[1] = __halves2bfloat162(l2, l3);
}

// transpose + split: src [R, C] fp32 -> dst[c][r] split bf16 (dst ld = R)
__global__ void k_tsplit(const float* __restrict__ src, int R, int C,
                         bf16* __restrict__ dhi, bf16* __restrict__ dlo) {
    __shared__ float t[32][33];
    int bx = blockIdx.x * 32;
    int by = blockIdx.y * 32;
    int tx = threadIdx.x, ty = threadIdx.y;
    #pragma unroll
    for (int i = 0; i < 4; i++)
        t[ty + 8 * i][tx] = src[(size_t)(by + ty + 8 * i) * C + bx + tx];
    __syncthreads();
    #pragma unroll
    for (int i = 0; i < 4; i++) {
        int c = bx + ty + 8 * i;
        float v = t[tx][ty + 8 * i];
        bf16 h, l; split2(v, h, l);
        dhi[(size_t)c * R + by + tx] = h;
        dlo[(size_t)c * R + by + tx] = l;
    }
}

// ---------------- fp16 single-product aggregation GEMM ----------------
// 128 threads, 4 warps (2m x 2n), BM=64, BN=128. Stage 24KB, 3 stages, 3 CTAs/SM.
#define AGG_STAGE 24576u
#define AGG_SMEM (3 * 24576)

__device__ __forceinline__ void agg_load_stage(
    uint32_t sb, int stage, int kc,
    const __half* A, int lda, const __half* B, int ldb,
    int m0, int n0, int tid) {
    uint32_t st = sb + (uint32_t)stage * AGG_STAGE;
    #pragma unroll
    for (int i = 0; i < 4; ++i) {           // A: 512 x 16B
        int g = tid + (i << 7);
        int row = g >> 3;
        int cb = (g & 7) << 4;
        uint32_t dst = st + (uint32_t)(row * 128) + (uint32_t)(cb ^ ((row & 7) << 4));
        CP16(dst, (const char*)(A + (size_t)(m0 + row) * lda + kc) + cb);
    }
    #pragma unroll
    for (int i = 0; i < 8; ++i) {           // B: 1024 x 16B
        int g = tid + (i << 7);
        int row = g >> 3;
        int cb = (g & 7) << 4;
        uint32_t dst = st + 8192u + (uint32_t)(row * 128) + (uint32_t)(cb ^ ((row & 7) << 4));
        CP16(dst, (const char*)(B + (size_t)(n0 + row) * ldb + kc) + cb);
    }
}

struct AggFrags { uint32_t ah[2][4], bh[4][4]; };

__device__ __forceinline__ void agg_frag_load(uint32_t aB, uint32_t bB, int kq,
                                              uint32_t acol, uint32_t axr,
                                              uint32_t bcol, uint32_t bxr, AggFrags& f) {
    uint32_t ac = ((uint32_t)(kq * 32) + acol) ^ axr;
    uint32_t bc = ((uint32_t)(kq * 32) + bcol) ^ bxr;
    #pragma unroll
    for (int mi = 0; mi < 2; ++mi)
        ldsm4(f.ah[mi], aB + (uint32_t)(mi * 2048) + ac);
    #pragma unroll
    for (int j = 0; j < 4; ++j)
        ldsm4(f.bh[j], bB + (uint32_t)(j * 2048) + bc);
}

__device__ __forceinline__ void agg_frag_mma(float acc[2][8][4], const AggFrags& f) {
    #pragma unroll
    for (int mi = 0; mi < 2; ++mi)
        #pragma unroll
        for (int ni = 0; ni < 8; ++ni)
            mma_f16(acc[mi][ni], f.ah[mi], &f.bh[ni >> 1][(ni & 1) * 2]);
}

__global__ void __launch_bounds__(128, 3)
k_agg(const __half* __restrict__ A, int lda, const __half* __restrict__ B, int ldb,
      int K, __half* __restrict__ of) {
    extern __shared__ char smem[];
    const int tid = threadIdx.x;
    const uint32_t sb = s2u(smem);
    const int m0 = (int)blockIdx.y * 64;
    const int n0 = (int)blockIdx.x * 128;
    const int CT = K >> 6;
    const int nz = (int)gridDim.z;
    const int c0 = (int)((size_t)blockIdx.z * CT / nz);
    const int c1 = (int)(((size_t)blockIdx.z + 1) * CT / nz);
    const int lane = tid & 31, wid = tid >> 5;
    const int wm = wid >> 1, wn = wid & 1;
    const int lg = lane >> 3, lr = lane & 7;

    const int arow = wm * 32 + (lg & 1) * 8 + lr;
    const uint32_t acol = (uint32_t)((lg >> 1) * 16);
    const uint32_t axr = (uint32_t)((arow & 7) << 4);
    const int brow = wn * 64 + (lg >> 1) * 8 + lr;
    const uint32_t bcol = (uint32_t)((lg & 1) * 16);
    const uint32_t bxr = (uint32_t)((brow & 7) << 4);

    float acc[2][8][4] = {};

    #pragma unroll
    for (int p = 0; p < 3; ++p) {
        agg_load_stage(sb, p, (c0 + p) << 6, A, lda, B, ldb, m0, n0, tid);
        asm volatile("cp.async.commit_group;" ::: "memory");
    }

    for (int c = c0; c < c1; ++c) {
        asm volatile("cp.async.wait_group 2;" ::: "memory");
        __syncthreads();

        int sidx = (c - c0) % 3;
        uint32_t st = sb + (uint32_t)(sidx * AGG_STAGE);
        uint32_t aB = st + (uint32_t)(arow * 128);
        uint32_t bB = st + 8192u + (uint32_t)(brow * 128);

        AggFrags f;
        #pragma unroll
        for (int kq = 0; kq < 3; ++kq) {
            agg_frag_load(aB, bB, kq, acol, axr, bcol, bxr, f);
            agg_frag_mma(acc, f);
        }
        agg_frag_load(aB, bB, 3, acol, axr, bcol, bxr, f);
        __syncthreads();
        int nc = c + 3;
        if (nc < c1)
            agg_load_stage(sb, sidx, nc << 6, A, lda, B, ldb, m0, n0, tid);
        asm volatile("cp.async.commit_group;" ::: "memory");
        agg_frag_mma(acc, f);
    }

    of += (size_t)blockIdx.z * NN * 128;
    #pragma unroll
    for (int mi = 0; mi < 2; ++mi) {
        int r0 = m0 + wm * 32 + mi * 16 + (lane >> 2);
        #pragma unroll
        for (int ni = 0; ni < 8; ++ni) {
            int c = n0 + wn * 64 + ni * 8 + ((lane & 3) << 1);
            *(__half2*)(of + (size_t)r0 * 128 + c) =
                __floats2half2_rn(acc[mi][ni][0], acc[mi][ni][1]);
            *(__half2*)(of + (size_t)(r0 + 8) * 128 + c) =
                __floats2half2_rn(acc[mi][ni][2], acc[mi][ni][3]);
        }
    }
}

// ---------------- bf16 3-product GEMM (linears), BM=64 BN=64 ----------------
// 128 threads, 4 warps (2m x 2n), per-warp m32 x n32. Stage 32KB, 2 stages,
// 3 CTAs/SM. grid (2, 128).
// mode 4: relu(v + sum(partials)*ISCALE + bias) -> split bf16 orm (ld_rm)
// mode 5: v + sum(partials)*ISCALE + bias -> fp32 of (ld Ncols), guard c < Ncols
// mode 6: v -> transposed fp16 yt (ld NN)
#define LIN_STAGE 32768u

__device__ __forceinline__ void lin_load_stage(
    uint32_t sb, int stage, int kc,
    const bf16* Ah, const bf16* Al, int lda,
    const bf16* Bh, const bf16* Bl, int ldb,
    int m0, int n0, int tid) {
    uint32_t st = sb + (uint32_t)stage * LIN_STAGE;
    #pragma unroll
    for (int i = 0; i < 8; ++i) {           // A: 1024 x 16B (hi+lo)
        int g = tid + (i << 7);
        int sub = g >> 9;
        int idx = g & 511;
        int row = idx >> 3;
        int cb = (idx & 7) << 4;
        uint32_t dst = st + (uint32_t)(sub * 8192) + (uint32_t)(row * 128)
                     + (uint32_t)(cb ^ ((row & 7) << 4));
        const bf16* srcb = sub ? Al : Ah;
        CP16(dst, (const char*)(srcb + (size_t)(m0 + row) * lda + kc) + cb);
    }
    #pragma unroll
    for (int i = 0; i < 8; ++i) {           // B: 1024 x 16B (hi+lo, 64 rows)
        int g = tid + (i << 7);
        int sub = g >> 9;
        int idx = g & 511;
        int row = idx >> 3;
        int cb = (idx & 7) << 4;
        uint32_t dst = st + 16384u + (uint32_t)(sub * 8192) + (uint32_t)(row * 128)
                     + (uint32_t)(cb ^ ((row & 7) << 4));
        const bf16* srcb = sub ? Bl : Bh;
        CP16(dst, (const char*)(srcb + (size_t)(n0 + row) * ldb + kc) + cb);
    }
}

struct Frags { uint32_t ah[2][4], al[2][4], bh[2][4], bl[2][4]; };

__device__ __forceinline__ void lin_frag_load(uint32_t aB, uint32_t bB, int kq,
                                              uint32_t acol, uint32_t axr,
                                              uint32_t bcol, uint32_t bxr, Frags& f) {
    uint32_t ac = ((uint32_t)(kq * 32) + acol) ^ axr;
    uint32_t bc = ((uint32_t)(kq * 32) + bcol) ^ bxr;
    #pragma unroll
    for (int mi = 0; mi < 2; ++mi) {
        ldsm4(f.ah[mi], aB + (uint32_t)(mi * 2048) + ac);
        ldsm4(f.al[mi], aB + 8192u + (uint32_t)(mi * 2048) + ac);
    }
    #pragma unroll
    for (int j = 0; j < 2; ++j) {
        ldsm4(f.bh[j], bB + (uint32_t)(j * 2048) + bc);
        ldsm4(f.bl[j], bB + 8192u + (uint32_t)(j * 2048) + bc);
    }
}

__device__ __forceinline__ void lin_frag_mma(float acc[2][4][4], const Frags& f) {
    #pragma unroll
    for (int mi = 0; mi < 2; ++mi)
        #pragma unroll
        for (int ni = 0; ni < 4; ++ni)
            mma_bf16(acc[mi][ni], f.ah[mi], &f.bh[ni >> 1][(ni & 1) * 2]);
    #pragma unroll
    for (int mi = 0; mi < 2; ++mi)
        #pragma unroll
        for (int ni = 0; ni < 4; ++ni)
            mma_bf16(acc[mi][ni], f.ah[mi], &f.bl[ni >> 1][(ni & 1) * 2]);
    #pragma unroll
    for (int mi = 0; mi < 2; ++mi)
        #pragma unroll
        for (int ni = 0; ni < 4; ++ni)
            mma_bf16(acc[mi][ni], f.al[mi], &f.bh[ni >> 1][(ni & 1) * 2]);
}

__global__ void __launch_bounds__(128, 3)
k_gemm(const bf16* __restrict__ Ah, const bf16* __restrict__ Al, int lda,
       const bf16* __restrict__ Bh, const bf16* __restrict__ Bl, int ldb,
       int K, int mode, int Ncols, const float* __restrict__ bias,
       const __half* __restrict__ zin,
       bf16* __restrict__ orm_hi, bf16* __restrict__ orm_lo, int ld_rm,
       __half* __restrict__ yt,
       float* __restrict__ of) {
    extern __shared__ char smem[];
    const int tid = threadIdx.x;
    const uint32_t sb = s2u(smem);
    const int m0 = (int)blockIdx.y * 64;
    const int n0 = (int)blockIdx.x * 64;
    const int C = K >> 6;
    const int lane = tid & 31, wid = tid >> 5;
    const int wm = wid >> 1, wn = wid & 1;
    const int lg = lane >> 3, lr = lane & 7;

    const int arow = wm * 32 + (lg & 1) * 8 + lr;
    const uint32_t acol = (uint32_t)((lg >> 1) * 16);
    const uint32_t axr = (uint32_t)((arow & 7) << 4);
    const int brow = wn * 32 + (lg >> 1) * 8 + lr;
    const uint32_t bcol = (uint32_t)((lg & 1) * 16);
    const uint32_t bxr = (uint32_t)((brow & 7) << 4);

    float acc[2][4][4] = {};

    lin_load_stage(sb, 0, 0, Ah, Al, lda, Bh, Bl, ldb, m0, n0, tid);
    asm volatile("cp.async.commit_group;" ::: "memory");
    lin_load_stage(sb, 1, 64, Ah, Al, lda, Bh, Bl, ldb, m0, n0, tid);
    asm volatile("cp.async.commit_group;" ::: "memory");

    for (int c = 0; c < C; ++c) {
        asm volatile("cp.async.wait_group 1;" ::: "memory");
        __syncthreads();

        uint32_t st = sb + (uint32_t)((c & 1) * LIN_STAGE);
        uint32_t aB = st + (uint32_t)(arow * 128);
        uint32_t bB = st + 16384u + (uint32_t)(brow * 128);

        Frags f;
        #pragma unroll
        for (int kq = 0; kq < 3; ++kq) {
            lin_frag_load(aB, bB, kq, acol, axr, bcol, bxr, f);
            lin_frag_mma(acc, f);
        }
        lin_frag_load(aB, bB, 3, acol, axr, bcol, bxr, f);
        __syncthreads();
        int nc = c + 2;
        if (nc < C)
            lin_load_stage(sb, c & 1, nc << 6, Ah, Al, lda, Bh, Bl, ldb, m0, n0, tid);
        asm volatile("cp.async.commit_group;" ::: "memory");
        lin_frag_mma(acc, f);
    }

    #pragma unroll
    for (int mi = 0; mi < 2; ++mi) {
        int r0 = m0 + wm * 32 + mi * 16 + (lane >> 2);
        #pragma unroll
        for (int ni = 0; ni < 4; ++ni) {
            int c = n0 + wn * 32 + ni * 8 + ((lane & 3) << 1);
            float v0 = acc[mi][ni][0], v1 = acc[mi][ni][1];
            float v2 = acc[mi][ni][2], v3 = acc[mi][ni][3];
            if (mode == 6) {
                yt[(size_t)c * NN + r0]           = __float2half_rn(v0);
                yt[(size_t)(c + 1) * NN + r0]     = __float2half_rn(v1);
                yt[(size_t)c * NN + r0 + 8]       = __float2half_rn(v2);
                yt[(size_t)(c + 1) * NN + r0 + 8] = __float2half_rn(v3);
            } else {
                // fused reduction of NZ_AGG fp16 partials (L2-hot)
                float z0 = 0.f, z1 = 0.f, z2 = 0.f, z3 = 0.f;
                #pragma unroll
                for (int q = 0; q < NZ_AGG; ++q) {
                    const __half* pq = zin + (size_t)q * NN * 128;
                    float2 fa = __half22float2(*(const __half2*)(pq + (size_t)r0 * 128 + c));
                    float2 fb = __half22float2(*(const __half2*)(pq + (size_t)(r0 + 8) * 128 + c));
                    z0 += fa.x; z1 += fa.y; z2 += fb.x; z3 += fb.y;
                }
                float b0v = bias[c], b1v = bias[c + 1];
                v0 += z0 * ADJ_ISCALE + b0v; v1 += z1 * ADJ_ISCALE + b1v;
                v2 += z2 * ADJ_ISCALE + b0v; v3 += z3 * ADJ_ISCALE + b1v;
                if (mode == 5) {
                    if (c < Ncols) {
                        *(float2*)(of + (size_t)r0 * Ncols + c)       = make_float2(v0, v1);
                        *(float2*)(of + (size_t)(r0 + 8) * Ncols + c) = make_float2(v2, v3);
                    }
                } else {  // mode 4
                    v0 = fmaxf(v0, 0.f); v1 = fmaxf(v1, 0.f);
                    v2 = fmaxf(v2, 0.f); v3 = fmaxf(v3, 0.f);
                    bf16 h0, l0, h1, l1, h2, l2, h3, l3;
                    split2(v0, h0, l0); split2(v1, h1, l1);
                    split2(v2, h2, l2); split2(v3, h3, l3);
                    *(__nv_bfloat162*)(orm_hi + (size_t)r0 * ld_rm + c) = __halves2bfloat162(h0, h1);
                    *(__nv_bfloat162*)(orm_lo + (size_t)r0 * ld_rm + c) = __halves2bfloat162(l0, l1);
                    *(__nv_bfloat162*)(orm_hi + (size_t)(r0 + 8) * ld_rm + c) = __halves2bfloat162(h2, h3);
                    *(__nv_bfloat162*)(orm_lo + (size_t)(r0 + 8) * ld_rm + c) = __halves2bfloat162(l2, l3);
                }
            }
        }
    }
}

// ---------------- host ----------------
static void* symaddr(const void* sym) {
    void* p = nullptr;
    cudaGetSymbolAddress(&p, sym);
    return p;
}

extern "C" void kernel_launch(void* const* d_in, const int* in_sizes, int n_in,
                              void* d_out, int out_size) {
    (void)in_sizes; (void)n_in; (void)out_size;
    const float* x   = (const float*)d_in[0];
    const float* adj = (const float*)d_in[1];
    const float* W1  = (const float*)d_in[2];
    const float* b1  = (const float*)d_in[3];
    const float* W2  = (const float*)d_in[4];
    const float* b2  = (const float*)d_in[5];
    const float* W3  = (const float*)d_in[6];
    const float* b3  = (const float*)d_in[7];
    const float* W4  = (const float*)d_in[8];
    const float* b4  = (const float*)d_in[9];

    __half* adjh = (__half*)symaddr(g_adj);
    bf16* x_hi   = (bf16*)symaddr(g_x_hi);
    bf16* x_lo   = (bf16*)symaddr(g_x_lo);
    bf16* hA_hi  = (bf16*)symaddr(g_hA_hi);
    bf16* hA_lo  = (bf16*)symaddr(g_hA_lo);
    bf16* hB_hi  = (bf16*)symaddr(g_hB_hi);
    bf16* hB_lo  = (bf16*)symaddr(g_hB_lo);
    __half* yt   = (__half*)symaddr(g_yt);
    bf16* wt_hi  = (bf16*)symaddr(g_wt_hi);
    bf16* wt_lo  = (bf16*)symaddr(g_wt_lo);
    __half* part = (__half*)symaddr(g_part);

    cudaFuncSetAttribute(k_gemm, cudaFuncAttributeMaxDynamicSharedMemorySize, 65536);
    cudaFuncSetAttribute(k_agg, cudaFuncAttributeMaxDynamicSharedMemorySize, AGG_SMEM);

    const dim3 gAgg(1, 128, NZ_AGG), gLin(2, 128, 1);

    // 1: adj fp16 (DRAM-bound, at roofline)
    k_split<<<4096, 256>>>((const float4*)adj, (uint4*)adjh, (size_t)NN * NN / 8);
    // 2: x split
    k_xcat<<<2048, 256>>>((const float4*)x, x_hi, x_lo);
    // 3: W1^T
    k_tsplit<<<dim3(4, 16), dim3(32, 8)>>>(W1, 512, 128, wt_hi, wt_lo);
    // 4: y1 = x @ W1_bot -> yt fp16  [PROFILED]
    k_gemm<<<gLin, 128, 65536>>>(x_hi, x_lo, 256, wt_hi + 256, wt_lo + 256, 512,
        256, 6, 128, nullptr, nullptr, nullptr, nullptr, 0, yt, nullptr);
    // 5: z1 partials = adj @ y1
    k_agg<<<gAgg, 128, AGG_SMEM>>>(adjh, NN, yt, NN, NN, part);
    // 6-8: remaining weight transposes (overlap agg tail)
    k_tsplit<<<dim3(4, 8), dim3(32, 8)>>>(W2, 256, 128, wt_hi + 65536,  wt_lo + 65536);
    k_tsplit<<<dim3(4, 8), dim3(32, 8)>>>(W3, 256, 128, wt_hi + 98304,  wt_lo + 98304);
    k_tsplit<<<dim3(2, 8), dim3(32, 8)>>>(W4, 256, 64,  wt_hi + 131072, wt_lo + 131072);
    // 9: h2 = relu(x @ W1_top + z + b1) -> hA   (fused partial reduction)
    k_gemm<<<gLin, 128, 65536>>>(x_hi, x_lo, 256, wt_hi, wt_lo, 512,
        256, 4, 128, b1, part, hA_hi, hA_lo, 128, nullptr, nullptr);

    // ---- layer 2 ----
    k_gemm<<<gLin, 128, 65536>>>(hA_hi, hA_lo, 128,
        wt_hi + 65536 + 128, wt_lo + 65536 + 128, 256,
        128, 6, 128, nullptr, nullptr, nullptr, nullptr, 0, yt, nullptr);
    k_agg<<<gAgg, 128, AGG_SMEM>>>(adjh, NN, yt, NN, NN, part);
    k_gemm<<<gLin, 128, 65536>>>(hA_hi, hA_lo, 128,
        wt_hi + 65536, wt_lo + 65536, 256,
        128, 4, 128, b2, part, hB_hi, hB_lo, 128, nullptr, nullptr);

    // ---- layer 3 ----
    k_gemm<<<gLin, 128, 65536>>>(hB_hi, hB_lo, 128,
        wt_hi + 98304 + 128, wt_lo + 98304 + 128, 256,
        128, 6, 128, nullptr, nullptr, nullptr, nullptr, 0, yt, nullptr);
    k_agg<<<gAgg, 128, AGG_SMEM>>>(adjh, NN, yt, NN, NN, part);
    k_gemm<<<gLin, 128, 65536>>>(hB_hi, hB_lo, 128,
        wt_hi + 98304, wt_lo + 98304, 256,
        128, 4, 128, b3, part, hA_hi, hA_lo, 128, nullptr, nullptr);

    // ---- layer 4 (N=64; W4^T rows 64..127 zero -> y/z cols 64..127 zero) ----
    k_gemm<<<gLin, 128, 65536>>>(hA_hi, hA_lo, 128,
        wt_hi + 131072 + 128, wt_lo + 131072 + 128, 256,
        128, 6, 128, nullptr, nullptr, nullptr, nullptr, 0, yt, nullptr);
    k_agg<<<gAgg, 128, AGG_SMEM>>>(adjh, NN, yt, NN, NN, part);
    k_gemm<<<gLin, 128, 65536>>>(hA_hi, hA_lo, 128,
        wt_hi + 131072, wt_lo + 131072, 256,
        128, 5, 64, b4, part, nullptr, nullptr, 0, nullptr, (float*)d_out);
}

// round 16
// speedup vs baseline: 2.3387x; 1.0266x over previous
#include <cuda_runtime.h>
#include <cuda_bf16.h>
#include <cuda_fp16.h>
#include <cstdint>
#include <cstddef>

typedef __nv_bfloat16 bf16;

#define NN 8192
#define ADJ_SCALE 4096.0f
#define ADJ_ISCALE (1.0f / 4096.0f)
#define NZ_AGG 10

// ---------------- device scratch (no allocs; zero-init at load) ----------------
__device__ __align__(1024) __half g_adj[(size_t)NN * NN];     // adj*4096 fp16
__device__ __align__(1024) bf16 g_x_hi[NN * 256];             // x split, ld 256
__device__ __align__(1024) bf16 g_x_lo[NN * 256];
__device__ __align__(1024) bf16 g_hA_hi[NN * 128];            // layer outputs ping-pong
__device__ __align__(1024) bf16 g_hA_lo[NN * 128];
__device__ __align__(1024) bf16 g_hB_hi[NN * 128];
__device__ __align__(1024) bf16 g_hB_lo[NN * 128];
__device__ __align__(1024) __half g_yt[128 * NN];             // y^T fp16 [128][NN]
__device__ __align__(1024) bf16 g_wt_hi[163840];              // stacked [W_top^T;W_bot^T]
__device__ __align__(1024) bf16 g_wt_lo[163840];
__device__ __align__(1024) float g_vt[NN * 128];              // v_top fp32
__device__ __align__(1024) __half g_part[(size_t)NZ_AGG * NN * 128];  // fp16 partials

// ---------------- helpers ----------------
__device__ __forceinline__ uint32_t s2u(const void* p) {
    uint32_t a;
    asm("{ .reg .u64 t; cvta.to.shared.u64 t, %1; cvt.u32.u64 %0, t; }" : "=r"(a) : "l"(p));
    return a;
}

#define CP16(dst_u32, src_ptr) \
    asm volatile("cp.async.cg.shared.global [%0], [%1], 16;" :: "r"(dst_u32), "l"(src_ptr) : "memory")

__device__ __forceinline__ void ldsm4(uint32_t a[4], uint32_t addr) {
    asm volatile("ldmatrix.sync.aligned.m8n8.x4.shared.b16 {%0,%1,%2,%3}, [%4];"
                 : "=r"(a[0]), "=r"(a[1]), "=r"(a[2]), "=r"(a[3]) : "r"(addr));
}

__device__ __forceinline__ void mma_bf16(float c[4], const uint32_t a[4], const uint32_t b[2]) {
    asm volatile(
        "mma.sync.aligned.m16n8k16.row.col.f32.bf16.bf16.f32 "
        "{%0,%1,%2,%3}, {%4,%5,%6,%7}, {%8,%9}, {%0,%1,%2,%3};"
        : "+f"(c[0]), "+f"(c[1]), "+f"(c[2]), "+f"(c[3])
        : "r"(a[0]), "r"(a[1]), "r"(a[2]), "r"(a[3]), "r"(b[0]), "r"(b[1]));
}

__device__ __forceinline__ void mma_f16(float c[4], const uint32_t a[4], const uint32_t b[2]) {
    asm volatile(
        "mma.sync.aligned.m16n8k16.row.col.f32.f16.f16.f32 "
        "{%0,%1,%2,%3}, {%4,%5,%6,%7}, {%8,%9}, {%0,%1,%2,%3};"
        : "+f"(c[0]), "+f"(c[1]), "+f"(c[2]), "+f"(c[3])
        : "r"(a[0]), "r"(a[1]), "r"(a[2]), "r"(a[3]), "r"(b[0]), "r"(b[1]));
}

__device__ __forceinline__ void split2(float v, bf16& h, bf16& l) {
    h = __float2bfloat16(v);
    l = __float2bfloat16(v - __bfloat162float(h));
}

// ---------------- prep kernels ----------------
// adj fp32 -> (adj*4096) single fp16; streaming
__global__ void k_split(const float4* __restrict__ src, uint4* __restrict__ dst,
                        size_t n8) {
    size_t i = (size_t)blockIdx.x * blockDim.x + threadIdx.x;
    size_t stride = (size_t)gridDim.x * blockDim.x;
    for (; i < n8; i += stride) {
        float4 a = __ldcs(src + 2 * i);
        float4 b = __ldcs(src + 2 * i + 1);
        uint4 H;
        __half2* Hp = (__half2*)&H;
        Hp[0] = __floats2half2_rn(a.x * ADJ_SCALE, a.y * ADJ_SCALE);
        Hp[1] = __floats2half2_rn(a.z * ADJ_SCALE, a.w * ADJ_SCALE);
        Hp[2] = __floats2half2_rn(b.x * ADJ_SCALE, b.y * ADJ_SCALE);
        Hp[3] = __floats2half2_rn(b.z * ADJ_SCALE, b.w * ADJ_SCALE);
        __stcs(dst + i, H);
    }
}

// x [8192,256] fp32 -> split row-major ld 256
__global__ void k_xcat(const float4* __restrict__ x4, bf16* __restrict__ hi,
                       bf16* __restrict__ lo) {
    int idx = blockIdx.x * blockDim.x + threadIdx.x;  // 8192*64
    float4 v = x4[idx];
    size_t base = (size_t)idx * 4;
    bf16 h0, h1, h2, h3, l0, l1, l2, l3;
    split2(v.x, h0, l0); split2(v.y, h1, l1);
    split2(v.z, h2, l2); split2(v.w, h3, l3);
    __nv_bfloat162* H = (__nv_bfloat162*)(hi + base);
    __nv_bfloat162* L = (__nv_bfloat162*)(lo + base);
    H[0] = __halves2bfloat162(h0, h1); H[1] = __halves2bfloat162(h2, h3);
    L[0] = __halves2bfloat162(l0, l1); L[1] = __halves2bfloat162(l2, l3);
}

// transpose + split: src [R, C] fp32 -> dst[c][r] split bf16 (dst ld = R)
__global__ void k_tsplit(const float* __restrict__ src, int R, int C,
                         bf16* __restrict__ dhi, bf16* __restrict__ dlo) {
    __shared__ float t[32][33];
    int bx = blockIdx.x * 32;
    int by = blockIdx.y * 32;
    int tx = threadIdx.x, ty = threadIdx.y;
    #pragma unroll
    for (int i = 0; i < 4; i++)
        t[ty + 8 * i][tx] = src[(size_t)(by + ty + 8 * i) * C + bx + tx];
    __syncthreads();
    #pragma unroll
    for (int i = 0; i < 4; i++) {
        int c = bx + ty + 8 * i;
        float v = t[tx][ty + 8 * i];
        bf16 h, l; split2(v, h, l);
        dhi[(size_t)c * R + by + tx] = h;
        dlo[(size_t)c * R + by + tx] = l;
    }
}

// post: h' = relu(vt + sum(partials)*ISCALE + bias) -> split bf16 (final=0)
//       out = vt + sum(partials)*ISCALE + bias -> fp32 [8192][64]   (final=1)
__global__ void k_post(const float4* __restrict__ vt4, const __half* __restrict__ part,
                       const float* __restrict__ bias,
                       bf16* __restrict__ ohi, bf16* __restrict__ olo,
                       float* __restrict__ ofin, int final_out) {
    int idx = blockIdx.x * blockDim.x + threadIdx.x;   // 8192*32
    int r = idx >> 5, c4 = (idx & 31) << 2;
    if (final_out && c4 >= 64) return;
    float4 v = vt4[idx];
    float z0 = 0.f, z1 = 0.f, z2 = 0.f, z3 = 0.f;
    #pragma unroll
    for (int q = 0; q < NZ_AGG; ++q) {
        const __half2* p2 = (const __half2*)(part + (size_t)q * NN * 128 + (size_t)r * 128 + c4);
        float2 a = __half22float2(p2[0]);
        float2 b = __half22float2(p2[1]);
        z0 += a.x; z1 += a.y; z2 += b.x; z3 += b.y;
    }
    v.x += z0 * ADJ_ISCALE + bias[c4];
    v.y += z1 * ADJ_ISCALE + bias[c4 + 1];
    v.z += z2 * ADJ_ISCALE + bias[c4 + 2];
    v.w += z3 * ADJ_ISCALE + bias[c4 + 3];
    if (final_out) {
        *(float4*)(ofin + (size_t)r * 64 + c4) = v;
    } else {
        v.x = fmaxf(v.x, 0.f); v.y = fmaxf(v.y, 0.f);
        v.z = fmaxf(v.z, 0.f); v.w = fmaxf(v.w, 0.f);
        bf16 h0, l0, h1, l1, h2, l2, h3, l3;
        split2(v.x, h0, l0); split2(v.y, h1, l1);
        split2(v.z, h2, l2); split2(v.w, h3, l3);
        __nv_bfloat162* H = (__nv_bfloat162*)(ohi + (size_t)r * 128 + c4);
        __nv_bfloat162* L = (__nv_bfloat162*)(olo + (size_t)r * 128 + c4);
        H[0] = __halves2bfloat162(h0, h1); H[1] = __halves2bfloat162(h2, h3);
        L[0] = __halves2bfloat162(l0, l1); L[1] = __halves2bfloat162(l2, l3);
    }
}

// ---------------- fp16 single-product aggregation GEMM ----------------
// 128 threads, 4 warps (2m x 2n), BM=64, BN=128. Stage 24KB, 3 stages, 3 CTAs/SM.
#define AGG_STAGE 24576u
#define AGG_SMEM (3 * 24576)

__device__ __forceinline__ void agg_load_stage(
    uint32_t sb, int stage, int kc,
    const __half* A, int lda, const __half* B, int ldb,
    int m0, int n0, int tid) {
    uint32_t st = sb + (uint32_t)stage * AGG_STAGE;
    #pragma unroll
    for (int i = 0; i < 4; ++i) {           // A: 512 x 16B
        int g = tid + (i << 7);
        int row = g >> 3;
        int cb = (g & 7) << 4;
        uint32_t dst = st + (uint32_t)(row * 128) + (uint32_t)(cb ^ ((row & 7) << 4));
        CP16(dst, (const char*)(A + (size_t)(m0 + row) * lda + kc) + cb);
    }
    #pragma unroll
    for (int i = 0; i < 8; ++i) {           // B: 1024 x 16B
        int g = tid + (i << 7);
        int row = g >> 3;
        int cb = (g & 7) << 4;
        uint32_t dst = st + 8192u + (uint32_t)(row * 128) + (uint32_t)(cb ^ ((row & 7) << 4));
        CP16(dst, (const char*)(B + (size_t)(n0 + row) * ldb + kc) + cb);
    }
}

struct AggFrags { uint32_t ah[2][4], bh[4][4]; };

__device__ __forceinline__ void agg_frag_load(uint32_t aB, uint32_t bB, int kq,
                                              uint32_t acol, uint32_t axr,
                                              uint32_t bcol, uint32_t bxr, AggFrags& f) {
    uint32_t ac = ((uint32_t)(kq * 32) + acol) ^ axr;
    uint32_t bc = ((uint32_t)(kq * 32) + bcol) ^ bxr;
    #pragma unroll
    for (int mi = 0; mi < 2; ++mi)
        ldsm4(f.ah[mi], aB + (uint32_t)(mi * 2048) + ac);
    #pragma unroll
    for (int j = 0; j < 4; ++j)
        ldsm4(f.bh[j], bB + (uint32_t)(j * 2048) + bc);
}

__device__ __forceinline__ void agg_frag_mma(float acc[2][8][4], const AggFrags& f) {
    #pragma unroll
    for (int mi = 0; mi < 2; ++mi)
        #pragma unroll
        for (int ni = 0; ni < 8; ++ni)
            mma_f16(acc[mi][ni], f.ah[mi], &f.bh[ni >> 1][(ni & 1) * 2]);
}

__global__ void __launch_bounds__(128, 3)
k_agg(const __half* __restrict__ A, int lda, const __half* __restrict__ B, int ldb,
      int K, __half* __restrict__ of) {
    extern __shared__ char smem[];
    const int tid = threadIdx.x;
    const uint32_t sb = s2u(smem);
    const int m0 = (int)blockIdx.y * 64;
    const int n0 = (int)blockIdx.x * 128;
    const int CT = K >> 6;
    const int nz = (int)gridDim.z;
    const int c0 = (int)((size_t)blockIdx.z * CT / nz);
    const int c1 = (int)(((size_t)blockIdx.z + 1) * CT / nz);
    const int lane = tid & 31, wid = tid >> 5;
    const int wm = wid >> 1, wn = wid & 1;
    const int lg = lane >> 3, lr = lane & 7;

    const int arow = wm * 32 + (lg & 1) * 8 + lr;
    const uint32_t acol = (uint32_t)((lg >> 1) * 16);
    const uint32_t axr = (uint32_t)((arow & 7) << 4);
    const int brow = wn * 64 + (lg >> 1) * 8 + lr;
    const uint32_t bcol = (uint32_t)((lg & 1) * 16);
    const uint32_t bxr = (uint32_t)((brow & 7) << 4);

    float acc[2][8][4] = {};

    #pragma unroll
    for (int p = 0; p < 3; ++p) {
        agg_load_stage(sb, p, (c0 + p) << 6, A, lda, B, ldb, m0, n0, tid);
        asm volatile("cp.async.commit_group;" ::: "memory");
    }

    for (int c = c0; c < c1; ++c) {
        asm volatile("cp.async.wait_group 2;" ::: "memory");
        __syncthreads();

        int sidx = (c - c0) % 3;
        uint32_t st = sb + (uint32_t)(sidx * AGG_STAGE);
        uint32_t aB = st + (uint32_t)(arow * 128);
        uint32_t bB = st + 8192u + (uint32_t)(brow * 128);

        AggFrags f;
        #pragma unroll
        for (int kq = 0; kq < 3; ++kq) {
            agg_frag_load(aB, bB, kq, acol, axr, bcol, bxr, f);
            agg_frag_mma(acc, f);
        }
        agg_frag_load(aB, bB, 3, acol, axr, bcol, bxr, f);
        __syncthreads();
        int nc = c + 3;
        if (nc < c1)
            agg_load_stage(sb, sidx, nc << 6, A, lda, B, ldb, m0, n0, tid);
        asm volatile("cp.async.commit_group;" ::: "memory");
        agg_frag_mma(acc, f);
    }

    of += (size_t)blockIdx.z * NN * 128;
    #pragma unroll
    for (int mi = 0; mi < 2; ++mi) {
        int r0 = m0 + wm * 32 + mi * 16 + (lane >> 2);
        #pragma unroll
        for (int ni = 0; ni < 8; ++ni) {
            int c = n0 + wn * 64 + ni * 8 + ((lane & 3) << 1);
            *(__half2*)(of + (size_t)r0 * 128 + c) =
                __floats2half2_rn(acc[mi][ni][0], acc[mi][ni][1]);
            *(__half2*)(of + (size_t)(r0 + 8) * 128 + c) =
                __floats2half2_rn(acc[mi][ni][2], acc[mi][ni][3]);
        }
    }
}

// ---------------- combined linear GEMM (bf16 3-product, BM=64 BN=64) --------
// grid (4, 128): N=256 over stacked B=[W_top^T ; W_bot^T].
// cols 0..127  -> vt fp32 [8192][128]
// cols 128..255-> yt fp16 transposed [128][NN]
#define LIN_STAGE 32768u

__device__ __forceinline__ void lin_load_stage(
    uint32_t sb, int stage, int kc,
    const bf16* Ah, const bf16* Al, int lda,
    const bf16* Bh, const bf16* Bl, int ldb,
    int m0, int n0, int tid) {
    uint32_t st = sb + (uint32_t)stage * LIN_STAGE;
    #pragma unroll
    for (int i = 0; i < 8; ++i) {           // A: 1024 x 16B (hi+lo)
        int g = tid + (i << 7);
        int sub = g >> 9;
        int idx = g & 511;
        int row = idx >> 3;
        int cb = (idx & 7) << 4;
        uint32_t dst = st + (uint32_t)(sub * 8192) + (uint32_t)(row * 128)
                     + (uint32_t)(cb ^ ((row & 7) << 4));
        const bf16* srcb = sub ? Al : Ah;
        CP16(dst, (const char*)(srcb + (size_t)(m0 + row) * lda + kc) + cb);
    }
    #pragma unroll
    for (int i = 0; i < 8; ++i) {           // B: 1024 x 16B (hi+lo, 64 rows)
        int g = tid + (i << 7);
        int sub = g >> 9;
        int idx = g & 511;
        int row = idx >> 3;
        int cb = (idx & 7) << 4;
        uint32_t dst = st + 16384u + (uint32_t)(sub * 8192) + (uint32_t)(row * 128)
                     + (uint32_t)(cb ^ ((row & 7) << 4));
        const bf16* srcb = sub ? Bl : Bh;
        CP16(dst, (const char*)(srcb + (size_t)(n0 + row) * ldb + kc) + cb);
    }
}

struct Frags { uint32_t ah[2][4], al[2][4], bh[2][4], bl[2][4]; };

__device__ __forceinline__ void lin_frag_load(uint32_t aB, uint32_t bB, int kq,
                                              uint32_t acol, uint32_t axr,
                                              uint32_t bcol, uint32_t bxr, Frags& f) {
    uint32_t ac = ((uint32_t)(kq * 32) + acol) ^ axr;
    uint32_t bc = ((uint32_t)(kq * 32) + bcol) ^ bxr;
    #pragma unroll
    for (int mi = 0; mi < 2; ++mi) {
        ldsm4(f.ah[mi], aB + (uint32_t)(mi * 2048) + ac);
        ldsm4(f.al[mi], aB + 8192u + (uint32_t)(mi * 2048) + ac);
    }
    #pragma unroll
    for (int j = 0; j < 2; ++j) {
        ldsm4(f.bh[j], bB + (uint32_t)(j * 2048) + bc);
        ldsm4(f.bl[j], bB + 8192u + (uint32_t)(j * 2048) + bc);
    }
}

__device__ __forceinline__ void lin_frag_mma(float acc[2][4][4], const Frags& f) {
    #pragma unroll
    for (int mi = 0; mi < 2; ++mi)
        #pragma unroll
        for (int ni = 0; ni < 4; ++ni)
            mma_bf16(acc[mi][ni], f.ah[mi], &f.bh[ni >> 1][(ni & 1) * 2]);
    #pragma unroll
    for (int mi = 0; mi < 2; ++mi)
        #pragma unroll
        for (int ni = 0; ni < 4; ++ni)
            mma_bf16(acc[mi][ni], f.ah[mi], &f.bl[ni >> 1][(ni & 1) * 2]);
    #pragma unroll
    for (int mi = 0; mi < 2; ++mi)
        #pragma unroll
        for (int ni = 0; ni < 4; ++ni)
            mma_bf16(acc[mi][ni], f.al[mi], &f.bh[ni >> 1][(ni & 1) * 2]);
}

__global__ void __launch_bounds__(128, 3)
k_gemm(const bf16* __restrict__ Ah, const bf16* __restrict__ Al, int lda,
       const bf16* __restrict__ Bh, const bf16* __restrict__ Bl, int ldb,
       int K, float* __restrict__ vt, __half* __restrict__ yt) {
    extern __shared__ char smem[];
    const int tid = threadIdx.x;
    const uint32_t sb = s2u(smem);
    const int m0 = (int)blockIdx.y * 64;
    const int n0 = (int)blockIdx.x * 64;
    const int C = K >> 6;
    const int lane = tid & 31, wid = tid >> 5;
    const int wm = wid >> 1, wn = wid & 1;
    const int lg = lane >> 3, lr = lane & 7;

    const int arow = wm * 32 + (lg & 1) * 8 + lr;
    const uint32_t acol = (uint32_t)((lg >> 1) * 16);
    const uint32_t axr = (uint32_t)((arow & 7) << 4);
    const int brow = wn * 32 + (lg >> 1) * 8 + lr;
    const uint32_t bcol = (uint32_t)((lg & 1) * 16);
    const uint32_t bxr = (uint32_t)((brow & 7) << 4);

    float acc[2][4][4] = {};

    lin_load_stage(sb, 0, 0, Ah, Al, lda, Bh, Bl, ldb, m0, n0, tid);
    asm volatile("cp.async.commit_group;" ::: "memory");
    lin_load_stage(sb, 1, 64, Ah, Al, lda, Bh, Bl, ldb, m0, n0, tid);
    asm volatile("cp.async.commit_group;" ::: "memory");

    for (int c = 0; c < C; ++c) {
        asm volatile("cp.async.wait_group 1;" ::: "memory");
        __syncthreads();

        uint32_t st = sb + (uint32_t)((c & 1) * LIN_STAGE);
        uint32_t aB = st + (uint32_t)(arow * 128);
        uint32_t bB = st + 16384u + (uint32_t)(brow * 128);

        Frags f;
        #pragma unroll
        for (int kq = 0; kq < 3; ++kq) {
            lin_frag_load(aB, bB, kq, acol, axr, bcol, bxr, f);
            lin_frag_mma(acc, f);
        }
        lin_frag_load(aB, bB, 3, acol, axr, bcol, bxr, f);
        __syncthreads();
        int nc = c + 2;
        if (nc < C)
            lin_load_stage(sb, c & 1, nc << 6, Ah, Al, lda, Bh, Bl, ldb, m0, n0, tid);
        asm volatile("cp.async.commit_group;" ::: "memory");
        lin_frag_mma(acc, f);
    }

    const bool top = (n0 < 128);
    #pragma unroll
    for (int mi = 0; mi < 2; ++mi) {
        int r0 = m0 + wm * 32 + mi * 16 + (lane >> 2);
        #pragma unroll
        for (int ni = 0; ni < 4; ++ni) {
            int c = n0 + wn * 32 + ni * 8 + ((lane & 3) << 1);
            float v0 = acc[mi][ni][0], v1 = acc[mi][ni][1];
            float v2 = acc[mi][ni][2], v3 = acc[mi][ni][3];
            if (top) {
                *(float2*)(vt + (size_t)r0 * 128 + c)       = make_float2(v0, v1);
                *(float2*)(vt + (size_t)(r0 + 8) * 128 + c) = make_float2(v2, v3);
            } else {
                int cc = c - 128;
                yt[(size_t)cc * NN + r0]           = __float2half_rn(v0);
                yt[(size_t)(cc + 1) * NN + r0]     = __float2half_rn(v1);
                yt[(size_t)cc * NN + r0 + 8]       = __float2half_rn(v2);
                yt[(size_t)(cc + 1) * NN + r0 + 8] = __float2half_rn(v3);
            }
        }
    }
}

// ---------------- host ----------------
static void* symaddr(const void* sym) {
    void* p = nullptr;
    cudaGetSymbolAddress(&p, sym);
    return p;
}

extern "C" void kernel_launch(void* const* d_in, const int* in_sizes, int n_in,
                              void* d_out, int out_size) {
    (void)in_sizes; (void)n_in; (void)out_size;
    const float* x   = (const float*)d_in[0];
    const float* adj = (const float*)d_in[1];
    const float* W1  = (const float*)d_in[2];
    const float* b1  = (const float*)d_in[3];
    const float* W2  = (const float*)d_in[4];
    const float* b2  = (const float*)d_in[5];
    const float* W3  = (const float*)d_in[6];
    const float* b3  = (const float*)d_in[7];
    const float* W4  = (const float*)d_in[8];
    const float* b4  = (const float*)d_in[9];

    __half* adjh = (__half*)symaddr(g_adj);
    bf16* x_hi   = (bf16*)symaddr(g_x_hi);
    bf16* x_lo   = (bf16*)symaddr(g_x_lo);
    bf16* hA_hi  = (bf16*)symaddr(g_hA_hi);
    bf16* hA_lo  = (bf16*)symaddr(g_hA_lo);
    bf16* hB_hi  = (bf16*)symaddr(g_hB_hi);
    bf16* hB_lo  = (bf16*)symaddr(g_hB_lo);
    __half* yt   = (__half*)symaddr(g_yt);
    bf16* wt_hi  = (bf16*)symaddr(g_wt_hi);
    bf16* wt_lo  = (bf16*)symaddr(g_wt_lo);
    float* vt    = (float*)symaddr(g_vt);
    __half* part = (__half*)symaddr(g_part);

    cudaFuncSetAttribute(k_gemm, cudaFuncAttributeMaxDynamicSharedMemorySize, 65536);
    cudaFuncSetAttribute(k_agg, cudaFuncAttributeMaxDynamicSharedMemorySize, AGG_SMEM);

    const dim3 gAgg(1, 128, NZ_AGG), gLin(4, 128, 1);

    // stacked weight offsets: wtc1@0 (ld 256), wtc2@65536, wtc3@98304, wtc4@131072 (ld 128)
    // 1: x split
    k_xcat<<<2048, 256>>>((const float4*)x, x_hi, x_lo);
    // 2-3: W1 top/bot -> stacked [256][256]
    k_tsplit<<<dim3(4, 8), dim3(32, 8)>>>(W1,             256, 128, wt_hi,         wt_lo);
    k_tsplit<<<dim3(4, 8), dim3(32, 8)>>>(W1 + 256 * 128, 256, 128, wt_hi + 32768, wt_lo + 32768);
    // 4: combined L1: vt = x@W1_top, y1 = x@W1_bot   [PROFILED]
    k_gemm<<<gLin, 128, 65536>>>(x_hi, x_lo, 256, wt_hi, wt_lo, 256, 256, vt, yt);
    // 5: adj fp16
    k_split<<<4096, 256>>>((const float4*)adj, (uint4*)adjh, (size_t)NN * NN / 8);
    // 6: z1 partials = adj @ y1
    k_agg<<<gAgg, 128, AGG_SMEM>>>(adjh, NN, yt, NN, NN, part);
    // 7-12: remaining stacked weights (overlap agg)
    k_tsplit<<<dim3(4, 4), dim3(32, 8)>>>(W2,             128, 128, wt_hi + 65536,          wt_lo + 65536);
    k_tsplit<<<dim3(4, 4), dim3(32, 8)>>>(W2 + 128 * 128, 128, 128, wt_hi + 65536 + 16384,  wt_lo + 65536 + 16384);
    k_tsplit<<<dim3(4, 4), dim3(32, 8)>>>(W3,             128, 128, wt_hi + 98304,          wt_lo + 98304);
    k_tsplit<<<dim3(4, 4), dim3(32, 8)>>>(W3 + 128 * 128, 128, 128, wt_hi + 98304 + 16384,  wt_lo + 98304 + 16384);
    k_tsplit<<<dim3(2, 4), dim3(32, 8)>>>(W4,             128, 64,  wt_hi + 131072,         wt_lo + 131072);
    k_tsplit<<<dim3(2, 4), dim3(32, 8)>>>(W4 + 128 * 64,  128, 64,  wt_hi + 131072 + 16384, wt_lo + 131072 + 16384);
    // 13: h2 = relu(vt + z1 + b1) -> hA
    k_post<<<1024, 256>>>((const float4*)vt, part, b1, hA_hi, hA_lo, nullptr, 0);

    // ---- layer 2 ----
    k_gemm<<<gLin, 128, 65536>>>(hA_hi, hA_lo, 128, wt_hi + 65536, wt_lo + 65536, 128,
                                 128, vt, yt);
    k_agg<<<gAgg, 128, AGG_SMEM>>>(adjh, NN, yt, NN, NN, part);
    k_post<<<1024, 256>>>((const float4*)vt, part, b2, hB_hi, hB_lo, nullptr, 0);

    // ---- layer 3 ----
    k_gemm<<<gLin, 128, 65536>>>(hB_hi, hB_lo, 128, wt_hi + 98304, wt_lo + 98304, 128,
                                 128, vt, yt);
    k_agg<<<gAgg, 128, AGG_SMEM>>>(adjh, NN, yt, NN, NN, part);
    k_post<<<1024, 256>>>((const float4*)vt, part, b3, hA_hi, hA_lo, nullptr, 0);

    // ---- layer 4 (N=64 zero-padded; final fp32 out) ----
    k_gemm<<<gLin, 128, 65536>>>(hA_hi, hA_lo, 128, wt_hi + 131072, wt_lo + 131072, 128,
                                 128, vt, yt);
    k_agg<<<gAgg, 128, AGG_SMEM>>>(adjh, NN, yt, NN, NN, part);
    k_post<<<1024, 256>>>((const float4*)vt, part, b4, nullptr, nullptr, (float*)d_out, 1);
}